// round 2
// baseline (speedup 1.0000x reference)
#include <cuda_runtime.h>
#include <cuda_bf16.h>

#define N_NODES 100000
#define N_EDGES 1600000
#define CH 128
#define SCAN_TILE 1024
#define N_TILES ((N_NODES + SCAN_TILE - 1) / SCAN_TILE)   // 98

// ---------------- scratch (static device globals; no allocation) ----------------
__device__ float g_bufA[N_NODES * CH];   // xw_scaled (GEMM output, both layers)
__device__ float g_bufB[N_NODES * CH];   // h (aggregation output, both layers)
__device__ int   g_deg[N_NODES];
__device__ float g_dinv[N_NODES];
__device__ int   g_rowptr[N_NODES + 1];
__device__ int   g_cursor[N_NODES];
__device__ int   g_col[N_EDGES];
__device__ int   g_tilesums[N_TILES];
__device__ float g_pool[CH];

// ---------------- graph preprocessing ----------------

__global__ void init_kernel() {
    int v = blockIdx.x * blockDim.x + threadIdx.x;
    if (v < N_NODES) g_deg[v] = 1;          // self loop
    if (v < CH) g_pool[v] = 0.f;
}

// NOTE: edge_index is int32 (JAX x64 disabled demotes the requested int64).
__global__ void hist_kernel(const int* __restrict__ ei) {
    int e = blockIdx.x * blockDim.x + threadIdx.x;
    if (e < N_EDGES) {
        int d = ei[N_EDGES + e];            // dst row
        atomicAdd(&g_deg[d], 1);
    }
}

__global__ void dinv_kernel() {
    int v = blockIdx.x * blockDim.x + threadIdx.x;
    if (v < N_NODES) g_dinv[v] = rsqrtf((float)g_deg[v]);
}

// exclusive scan of (deg-1) -> rowptr (tile-local), tile sums out
__global__ void scan1_kernel() {
    __shared__ int sh[SCAN_TILE];
    int t = threadIdx.x;
    int v = blockIdx.x * SCAN_TILE + t;
    int c = (v < N_NODES) ? (g_deg[v] - 1) : 0;
    sh[t] = c;
    __syncthreads();
    #pragma unroll
    for (int off = 1; off < SCAN_TILE; off <<= 1) {
        int val = (t >= off) ? sh[t - off] : 0;
        __syncthreads();
        sh[t] += val;
        __syncthreads();
    }
    if (v < N_NODES) g_rowptr[v] = sh[t] - c;   // exclusive, tile-local
    if (t == SCAN_TILE - 1) g_tilesums[blockIdx.x] = sh[t];
}

__global__ void scan2_kernel() {
    if (threadIdx.x == 0) {
        int run = 0;
        for (int i = 0; i < N_TILES; ++i) {
            int tmp = g_tilesums[i];
            g_tilesums[i] = run;
            run += tmp;
        }
    }
}

__global__ void scan3_kernel() {
    int v = blockIdx.x * blockDim.x + threadIdx.x;
    if (v < N_NODES) {
        int r = g_rowptr[v] + g_tilesums[v >> 10];
        g_rowptr[v] = r;
        g_cursor[v] = r;
    }
    if (v == 0) g_rowptr[N_NODES] = N_EDGES;
}

__global__ void fill_kernel(const int* __restrict__ ei) {
    int e = blockIdx.x * blockDim.x + threadIdx.x;
    if (e < N_EDGES) {
        int s = ei[e];
        int d = ei[N_EDGES + e];
        int p = atomicAdd(&g_cursor[d], 1);
        g_col[p] = s;
    }
}

// ---------------- GEMM: out = (A @ W) * dinv[row], out = g_bufA ----------------
// tile 128x128, K=128 one shot. 256 threads, 8x8 micro-tile per thread.
__global__ void gemm_scale_kernel(const float* __restrict__ Aext,
                                  const float* __restrict__ W,
                                  int useInternal) {
    extern __shared__ float sh[];
    float* AsT = sh;               // [128][129], k-major: AsT[k*129 + row]
    float* Ws  = sh + 128 * 129;   // [128][128]: Ws[k*128 + col]
    const float* A = useInternal ? g_bufB : Aext;
    float* out = g_bufA;

    int t = threadIdx.x;                 // 0..255
    int row0 = blockIdx.x * 128;

    // load A tile (coalesced gmem, conflict-free smem: stride 129)
    #pragma unroll 8
    for (int i = 0; i < 64; ++i) {
        int idx = t + i * 256;
        int r = idx >> 7, k = idx & 127;
        int grow = row0 + r;
        float v = (grow < N_NODES) ? A[grow * CH + k] : 0.f;
        AsT[k * 129 + r] = v;
    }
    // load W
    #pragma unroll 8
    for (int i = 0; i < 64; ++i) {
        int idx = t + i * 256;
        Ws[idx] = W[idx];
    }
    __syncthreads();

    int tx = t & 15, ty = t >> 4;
    float acc[8][8];
    #pragma unroll
    for (int i = 0; i < 8; ++i)
        #pragma unroll
        for (int j = 0; j < 8; ++j) acc[i][j] = 0.f;

    for (int k = 0; k < 128; ++k) {
        float a[8], b[8];
        const float* ap = &AsT[k * 129 + ty];
        const float* bp = &Ws[k * 128 + tx];
        #pragma unroll
        for (int i = 0; i < 8; ++i) a[i] = ap[16 * i];
        #pragma unroll
        for (int j = 0; j < 8; ++j) b[j] = bp[16 * j];
        #pragma unroll
        for (int i = 0; i < 8; ++i)
            #pragma unroll
            for (int j = 0; j < 8; ++j)
                acc[i][j] += a[i] * b[j];
    }

    #pragma unroll
    for (int i = 0; i < 8; ++i) {
        int r = row0 + ty + 16 * i;
        if (r < N_NODES) {
            float d = g_dinv[r];
            #pragma unroll
            for (int j = 0; j < 8; ++j)
                out[r * CH + tx + 16 * j] = acc[i][j] * d;
        }
    }
}

// ---------------- aggregation: one warp per node ----------------
// h[v] = relu(dinv[v] * (xws[v] + sum_{u->v} xws[u]) + bias)
__global__ void agg_kernel(const float* __restrict__ bias) {
    int warp = (blockIdx.x * blockDim.x + threadIdx.x) >> 5;
    int lane = threadIdx.x & 31;
    if (warp >= N_NODES) return;
    int v = warp;
    const float4* base = (const float4*)g_bufA;
    float4 acc = base[v * 32 + lane];                 // self loop term
    int s = g_rowptr[v], e = g_rowptr[v + 1];
    int i = s;
    for (; i + 3 < e; i += 4) {
        int u0 = g_col[i], u1 = g_col[i + 1], u2 = g_col[i + 2], u3 = g_col[i + 3];
        float4 m0 = base[u0 * 32 + lane];
        float4 m1 = base[u1 * 32 + lane];
        float4 m2 = base[u2 * 32 + lane];
        float4 m3 = base[u3 * 32 + lane];
        acc.x += m0.x + m1.x + m2.x + m3.x;
        acc.y += m0.y + m1.y + m2.y + m3.y;
        acc.z += m0.z + m1.z + m2.z + m3.z;
        acc.w += m0.w + m1.w + m2.w + m3.w;
    }
    for (; i < e; ++i) {
        int u = g_col[i];
        float4 m = base[u * 32 + lane];
        acc.x += m.x; acc.y += m.y; acc.z += m.z; acc.w += m.w;
    }
    float d = g_dinv[v];
    float4 bb = ((const float4*)bias)[lane];
    acc.x = fmaxf(acc.x * d + bb.x, 0.f);
    acc.y = fmaxf(acc.y * d + bb.y, 0.f);
    acc.z = fmaxf(acc.z * d + bb.z, 0.f);
    acc.w = fmaxf(acc.w * d + bb.w, 0.f);
    ((float4*)g_bufB)[v * 32 + lane] = acc;
}

// ---------------- pooling: column sums of g_bufB ----------------
__global__ void pool_kernel() {
    int c = threadIdx.x;   // 128 threads
    float s = 0.f;
    for (int r = blockIdx.x; r < N_NODES; r += gridDim.x)
        s += g_bufB[r * CH + c];
    atomicAdd(&g_pool[c], s);
}

// ---------------- final FC: out = (pool/N) @ Wfc + bfc ----------------
__global__ void fc_kernel(const float* __restrict__ Wfc,
                          const float* __restrict__ bfc,
                          float* __restrict__ out) {
    __shared__ float p[CH];
    int j = threadIdx.x;
    p[j] = g_pool[j] * (1.0f / (float)N_NODES);
    __syncthreads();
    float s = bfc[j];
    #pragma unroll 16
    for (int i = 0; i < CH; ++i)
        s += p[i] * Wfc[i * CH + j];
    out[j] = s;
}

// ---------------- launch ----------------
extern "C" void kernel_launch(void* const* d_in, const int* in_sizes, int n_in,
                              void* d_out, int out_size) {
    const float* x   = (const float*)d_in[0];
    const int*   ei  = (const int*)d_in[1];      // int32! (JAX demotes int64)
    const float* W1  = (const float*)d_in[2];
    const float* b1  = (const float*)d_in[3];
    const float* W2  = (const float*)d_in[4];
    const float* b2  = (const float*)d_in[5];
    const float* Wfc = (const float*)d_in[6];
    const float* bfc = (const float*)d_in[7];
    float* out = (float*)d_out;

    const int nodeBlocks = (N_NODES + 255) / 256;
    const int edgeBlocks = (N_EDGES + 255) / 256;
    const int gemmBlocks = (N_NODES + 127) / 128;
    const int aggBlocks  = (N_NODES * 32 + 255) / 256;
    const int gemmSmem   = (128 * 129 + 128 * 128) * sizeof(float);   // ~128.5 KB

    cudaFuncSetAttribute(gemm_scale_kernel,
                         cudaFuncAttributeMaxDynamicSharedMemorySize, gemmSmem);

    // preprocessing: degrees, dinv, CSR by dst
    init_kernel<<<nodeBlocks, 256>>>();
    hist_kernel<<<edgeBlocks, 256>>>(ei);
    dinv_kernel<<<nodeBlocks, 256>>>();
    scan1_kernel<<<N_TILES, SCAN_TILE>>>();
    scan2_kernel<<<1, 32>>>();
    scan3_kernel<<<nodeBlocks, 256>>>();
    fill_kernel<<<edgeBlocks, 256>>>(ei);

    // layer 1
    gemm_scale_kernel<<<gemmBlocks, 256, gemmSmem>>>(x, W1, 0);
    agg_kernel<<<aggBlocks, 256>>>(b1);
    // layer 2
    gemm_scale_kernel<<<gemmBlocks, 256, gemmSmem>>>(nullptr, W2, 1);
    agg_kernel<<<aggBlocks, 256>>>(b2);

    // mean pool + FC
    pool_kernel<<<512, CH>>>();
    fc_kernel<<<1, CH>>>(Wfc, bfc, out);
}

// round 6
// speedup vs baseline: 1.2002x; 1.2002x over previous
#include <cuda_runtime.h>
#include <cuda_bf16.h>
#include <mma.h>
#include <cstdint>

using namespace nvcuda;

#define N_NODES 100000
#define N_EDGES 1600000
#define CH 128
#define SCAN_TILE 1024
#define N_TILES ((N_NODES + SCAN_TILE - 1) / SCAN_TILE)   // 98

// ---------------- scratch (static device globals; no allocation) ----------------
__device__ float g_bufA[N_NODES * CH];   // xw_scaled (GEMM output, both layers)
__device__ float g_bufB[N_NODES * CH];   // h (aggregation output, both layers)
__device__ int   g_deg[N_NODES];
__device__ float g_dinv[N_NODES];
__device__ int   g_rowptr[N_NODES + 1];
__device__ int   g_cursor[N_NODES];
__device__ int   g_col[N_EDGES];
__device__ int   g_tilesums[N_TILES];
__device__ float g_pool[CH];

// pre-split bf16 weights, row-major [k][n]  (128x128 bf16 = 32KB each)
__device__ __nv_bfloat16 g_W1_hi[CH * CH];
__device__ __nv_bfloat16 g_W1_lo[CH * CH];
__device__ __nv_bfloat16 g_W2_hi[CH * CH];
__device__ __nv_bfloat16 g_W2_lo[CH * CH];

// ---------------- graph preprocessing ----------------

__global__ void init_kernel() {
    int v = blockIdx.x * blockDim.x + threadIdx.x;
    if (v < N_NODES) g_deg[v] = 1;          // self loop
    if (v < CH) g_pool[v] = 0.f;
}

__global__ void hist_kernel(const int* __restrict__ ei) {
    int e = blockIdx.x * blockDim.x + threadIdx.x;
    if (e < N_EDGES) atomicAdd(&g_deg[ei[N_EDGES + e]], 1);
}

__global__ void dinv_kernel() {
    int v = blockIdx.x * blockDim.x + threadIdx.x;
    if (v < N_NODES) g_dinv[v] = rsqrtf((float)g_deg[v]);
}

__global__ void scan1_kernel() {
    __shared__ int sh[SCAN_TILE];
    int t = threadIdx.x;
    int v = blockIdx.x * SCAN_TILE + t;
    int c = (v < N_NODES) ? (g_deg[v] - 1) : 0;
    sh[t] = c;
    __syncthreads();
    #pragma unroll
    for (int off = 1; off < SCAN_TILE; off <<= 1) {
        int val = (t >= off) ? sh[t - off] : 0;
        __syncthreads();
        sh[t] += val;
        __syncthreads();
    }
    if (v < N_NODES) g_rowptr[v] = sh[t] - c;
    if (t == SCAN_TILE - 1) g_tilesums[blockIdx.x] = sh[t];
}

__global__ void scan2_kernel() {
    if (threadIdx.x == 0) {
        int run = 0;
        for (int i = 0; i < N_TILES; ++i) { int tmp = g_tilesums[i]; g_tilesums[i] = run; run += tmp; }
    }
}

__global__ void scan3_kernel() {
    int v = blockIdx.x * blockDim.x + threadIdx.x;
    if (v < N_NODES) {
        int r = g_rowptr[v] + g_tilesums[v >> 10];
        g_rowptr[v] = r;
        g_cursor[v] = r;
    }
    if (v == 0) g_rowptr[N_NODES] = N_EDGES;
}

__global__ void fill_kernel(const int* __restrict__ ei) {
    int e = blockIdx.x * blockDim.x + threadIdx.x;
    if (e < N_EDGES) {
        int s = ei[e];
        int d = ei[N_EDGES + e];
        int p = atomicAdd(&g_cursor[d], 1);
        g_col[p] = s;
    }
}

// ---------------- weight prep: split W into bf16 hi/lo, row-major [k][n] ----------------
__global__ void wprep_kernel(const float* __restrict__ W1, const float* __restrict__ W2) {
    const float* W = (blockIdx.x == 0) ? W1 : W2;
    __nv_bfloat16* hi = (blockIdx.x == 0) ? g_W1_hi : g_W2_hi;
    __nv_bfloat16* lo = (blockIdx.x == 0) ? g_W1_lo : g_W2_lo;
    for (int idx = threadIdx.x; idx < CH * CH; idx += blockDim.x) {
        float v = W[idx];
        __nv_bfloat16 h = __float2bfloat16(v);
        __nv_bfloat16 l = __float2bfloat16(v - __bfloat162float(h));
        hi[idx] = h;
        lo[idx] = l;
    }
}

// ---------------- GEMM via wmma (legacy HMMA): out = (A @ W) * dinv[row] ----------------
// CTA tile M=128 N=128 K=128. 256 threads = 8 warps in 2(m) x 4(n) grid;
// each warp computes 64x32 via 4x2 wmma 16x16x16 tiles.
// bf16 hi/lo 3-term split -> ~4e-6 relative error, fp32 accumulate.
#define LDT 136                      // padded bf16 leading dim (mult of 8)
#define TILE_B (128 * LDT)           // bf16 elems per tile
#define SM_AHI 0
#define SM_ALO (TILE_B)
#define SM_BHI (2 * TILE_B)
#define SM_BLO (3 * TILE_B)
#define GEMM_SMEM (4 * TILE_B * 2)   // 139264 bytes

__global__ void __launch_bounds__(256, 1)
gemm_wmma_kernel(const float* __restrict__ Aext, int useInternal, int layer) {
    extern __shared__ __nv_bfloat16 sm[];
    const float* A = useInternal ? g_bufB : Aext;
    const __nv_bfloat16* Wh = (layer == 0) ? g_W1_hi : g_W2_hi;
    const __nv_bfloat16* Wl = (layer == 0) ? g_W1_lo : g_W2_lo;

    int tid = threadIdx.x;
    int row0 = blockIdx.x * 128;

    // ---- load A tile: fp32 -> bf16 hi/lo, row-major padded ----
    #pragma unroll 4
    for (int i = 0; i < 32; ++i) {
        int p = tid + (i << 8);          // 0..8191 float2 slots
        int row = p >> 6;                // 0..127
        int cp  = p & 63;                // float2 col
        int gr = row0 + row;
        float2 v = (gr < N_NODES) ? ((const float2*)A)[gr * 64 + cp]
                                  : make_float2(0.f, 0.f);
        __nv_bfloat16 h0 = __float2bfloat16(v.x);
        __nv_bfloat16 h1 = __float2bfloat16(v.y);
        __nv_bfloat16 l0 = __float2bfloat16(v.x - __bfloat162float(h0));
        __nv_bfloat16 l1 = __float2bfloat16(v.y - __bfloat162float(h1));
        int o = row * LDT + cp * 2;
        sm[SM_AHI + o] = h0; sm[SM_AHI + o + 1] = h1;
        sm[SM_ALO + o] = l0; sm[SM_ALO + o + 1] = l1;
    }
    // ---- copy W tiles (row-major, 16B chunks, padded rows stay 16B-aligned) ----
    #pragma unroll
    for (int i = 0; i < 8; ++i) {
        int j = tid + (i << 8);          // 0..2047 uint4 chunks
        int row = j >> 4, q = j & 15;
        int dst = (row * LDT + q * 8) >> 3;     // uint4 index (LDT*2 bytes = 272, 16B-aligned)
        int src = j;
        ((uint4*)(sm + SM_BHI))[dst] = ((const uint4*)Wh)[src];
        ((uint4*)(sm + SM_BLO))[dst] = ((const uint4*)Wl)[src];
    }
    __syncthreads();

    int w = tid >> 5;
    int wm = w >> 2;          // 0..1 -> rows [wm*64, +64)
    int wn = w & 3;           // 0..3 -> cols [wn*32, +32)

    wmma::fragment<wmma::accumulator, 16, 16, 16, float> acc[4][2];
    #pragma unroll
    for (int mi = 0; mi < 4; ++mi)
        #pragma unroll
        for (int nj = 0; nj < 2; ++nj)
            wmma::fill_fragment(acc[mi][nj], 0.f);

    #pragma unroll
    for (int kk = 0; kk < 8; ++kk) {
        wmma::fragment<wmma::matrix_b, 16, 16, 16, __nv_bfloat16, wmma::row_major> bhi[2], blo[2];
        #pragma unroll
        for (int nj = 0; nj < 2; ++nj) {
            int boff = (kk * 16) * LDT + wn * 32 + nj * 16;
            wmma::load_matrix_sync(bhi[nj], sm + SM_BHI + boff, LDT);
            wmma::load_matrix_sync(blo[nj], sm + SM_BLO + boff, LDT);
        }
        #pragma unroll
        for (int mi = 0; mi < 4; ++mi) {
            wmma::fragment<wmma::matrix_a, 16, 16, 16, __nv_bfloat16, wmma::row_major> ahi, alo;
            int aoff = (wm * 64 + mi * 16) * LDT + kk * 16;
            wmma::load_matrix_sync(ahi, sm + SM_AHI + aoff, LDT);
            wmma::load_matrix_sync(alo, sm + SM_ALO + aoff, LDT);
            #pragma unroll
            for (int nj = 0; nj < 2; ++nj) {
                wmma::mma_sync(acc[mi][nj], ahi, bhi[nj], acc[mi][nj]);
                wmma::mma_sync(acc[mi][nj], alo, bhi[nj], acc[mi][nj]);
                wmma::mma_sync(acc[mi][nj], ahi, blo[nj], acc[mi][nj]);
            }
        }
    }

    // ---- epilogue: park fp32 C in smem (reuse tile space), scale by dinv, store ----
    __syncthreads();
    float* C = (float*)sm;                    // 128x128 fp32 = 64KB
    #pragma unroll
    for (int mi = 0; mi < 4; ++mi)
        #pragma unroll
        for (int nj = 0; nj < 2; ++nj)
            wmma::store_matrix_sync(C + (wm * 64 + mi * 16) * 128 + wn * 32 + nj * 16,
                                    acc[mi][nj], 128, wmma::mem_row_major);
    __syncthreads();

    int r    = tid >> 1;                      // 0..127
    int half = tid & 1;                       // 0..1 (64 cols each)
    int gr = row0 + r;
    if (gr < N_NODES) {
        float dv = g_dinv[gr];
        const float4* cs = (const float4*)(C + r * 128) + half * 16;
        float4* od = (float4*)(g_bufA + gr * CH) + half * 16;
        #pragma unroll
        for (int q = 0; q < 16; ++q) {
            float4 v = cs[q];
            v.x *= dv; v.y *= dv; v.z *= dv; v.w *= dv;
            od[q] = v;
        }
    }
}

// ---------------- aggregation: one warp per node ----------------
__global__ void agg_kernel(const float* __restrict__ bias) {
    int warp = (blockIdx.x * blockDim.x + threadIdx.x) >> 5;
    int lane = threadIdx.x & 31;
    if (warp >= N_NODES) return;
    int v = warp;
    const float4* base = (const float4*)g_bufA;
    float4 acc = base[v * 32 + lane];                 // self loop term
    int s = g_rowptr[v], e = g_rowptr[v + 1];
    int i = s;
    for (; i + 3 < e; i += 4) {
        int u0 = g_col[i], u1 = g_col[i + 1], u2 = g_col[i + 2], u3 = g_col[i + 3];
        float4 m0 = base[u0 * 32 + lane];
        float4 m1 = base[u1 * 32 + lane];
        float4 m2 = base[u2 * 32 + lane];
        float4 m3 = base[u3 * 32 + lane];
        acc.x += m0.x + m1.x + m2.x + m3.x;
        acc.y += m0.y + m1.y + m2.y + m3.y;
        acc.z += m0.z + m1.z + m2.z + m3.z;
        acc.w += m0.w + m1.w + m2.w + m3.w;
    }
    for (; i < e; ++i) {
        int u = g_col[i];
        float4 m = base[u * 32 + lane];
        acc.x += m.x; acc.y += m.y; acc.z += m.z; acc.w += m.w;
    }
    float d = g_dinv[v];
    float4 bb = ((const float4*)bias)[lane];
    acc.x = fmaxf(acc.x * d + bb.x, 0.f);
    acc.y = fmaxf(acc.y * d + bb.y, 0.f);
    acc.z = fmaxf(acc.z * d + bb.z, 0.f);
    acc.w = fmaxf(acc.w * d + bb.w, 0.f);
    ((float4*)g_bufB)[v * 32 + lane] = acc;
}

// ---------------- pooling ----------------
__global__ void pool_kernel() {
    int c = threadIdx.x;
    float s = 0.f;
    for (int r = blockIdx.x; r < N_NODES; r += gridDim.x)
        s += g_bufB[r * CH + c];
    atomicAdd(&g_pool[c], s);
}

// ---------------- final FC ----------------
__global__ void fc_kernel(const float* __restrict__ Wfc,
                          const float* __restrict__ bfc,
                          float* __restrict__ out) {
    __shared__ float p[CH];
    int j = threadIdx.x;
    p[j] = g_pool[j] * (1.0f / (float)N_NODES);
    __syncthreads();
    float s = bfc[j];
    #pragma unroll 16
    for (int i = 0; i < CH; ++i)
        s += p[i] * Wfc[i * CH + j];
    out[j] = s;
}

// ---------------- launch ----------------
extern "C" void kernel_launch(void* const* d_in, const int* in_sizes, int n_in,
                              void* d_out, int out_size) {
    const float* x   = (const float*)d_in[0];
    const int*   ei  = (const int*)d_in[1];      // int32 (JAX demotes int64)
    const float* W1  = (const float*)d_in[2];
    const float* b1  = (const float*)d_in[3];
    const float* W2  = (const float*)d_in[4];
    const float* b2  = (const float*)d_in[5];
    const float* Wfc = (const float*)d_in[6];
    const float* bfc = (const float*)d_in[7];
    float* out = (float*)d_out;

    const int nodeBlocks = (N_NODES + 255) / 256;
    const int edgeBlocks = (N_EDGES + 255) / 256;
    const int gemmBlocks = (N_NODES + 127) / 128;   // 782
    const int aggBlocks  = (N_NODES * 32 + 255) / 256;

    cudaFuncSetAttribute(gemm_wmma_kernel,
                         cudaFuncAttributeMaxDynamicSharedMemorySize, GEMM_SMEM);

    // preprocessing: degrees, dinv, CSR by dst, weight split
    init_kernel<<<nodeBlocks, 256>>>();
    hist_kernel<<<edgeBlocks, 256>>>(ei);
    wprep_kernel<<<2, 256>>>(W1, W2);
    dinv_kernel<<<nodeBlocks, 256>>>();
    scan1_kernel<<<N_TILES, SCAN_TILE>>>();
    scan2_kernel<<<1, 32>>>();
    scan3_kernel<<<nodeBlocks, 256>>>();
    fill_kernel<<<edgeBlocks, 256>>>(ei);

    // layer 1
    gemm_wmma_kernel<<<gemmBlocks, 256, GEMM_SMEM>>>(x, 0, 0);
    agg_kernel<<<aggBlocks, 256>>>(b1);
    // layer 2
    gemm_wmma_kernel<<<gemmBlocks, 256, GEMM_SMEM>>>(nullptr, 1, 1);
    agg_kernel<<<aggBlocks, 256>>>(b2);

    // mean pool + FC
    pool_kernel<<<512, CH>>>();
    fc_kernel<<<1, CH>>>(Wfc, bfc, out);
}

// round 9
// speedup vs baseline: 1.6508x; 1.3754x over previous
#include <cuda_runtime.h>
#include <cuda_bf16.h>
#include <mma.h>
#include <cstdint>

using namespace nvcuda;

#define N_NODES 100000
#define N_EDGES 1600000
#define CH 128
#define SCAN_TILE 1024
#define N_TILES ((N_NODES + SCAN_TILE - 1) / SCAN_TILE)   // 98

// ---------------- scratch (static device globals; no allocation) ----------------
__device__ uint32_t g_bufA16[N_NODES * 64];  // xw_scaled, packed bf16x2 [N][64]
__device__ float    g_bufB[N_NODES * CH];    // h1 (agg1 output, fp32 for GEMM2)
__device__ int   g_deg[N_NODES];
__device__ float g_dinv[N_NODES];
__device__ int   g_rowptr[N_NODES + 1];
__device__ int   g_cursor[N_NODES];
__device__ int   g_col[N_EDGES];
__device__ int   g_tilesums[N_TILES];
__device__ float g_pool[CH];

// pre-split bf16 weights, row-major [k][n]  (128x128 bf16 = 32KB each)
__device__ __nv_bfloat16 g_W1_hi[CH * CH];
__device__ __nv_bfloat16 g_W1_lo[CH * CH];
__device__ __nv_bfloat16 g_W2_hi[CH * CH];
__device__ __nv_bfloat16 g_W2_lo[CH * CH];

__device__ __forceinline__ uint32_t pack_bf2(float a, float b) {
    __nv_bfloat162 t = __floats2bfloat162_rn(a, b);
    return *(uint32_t*)&t;
}

// ---------------- graph preprocessing ----------------

__global__ void init_kernel() {
    int v = blockIdx.x * blockDim.x + threadIdx.x;
    if (v < N_NODES) g_deg[v] = 1;          // self loop
    if (v < CH) g_pool[v] = 0.f;
}

__global__ void hist_kernel(const int* __restrict__ ei) {
    int e = blockIdx.x * blockDim.x + threadIdx.x;
    if (e < N_EDGES) atomicAdd(&g_deg[ei[N_EDGES + e]], 1);
}

__global__ void dinv_kernel() {
    int v = blockIdx.x * blockDim.x + threadIdx.x;
    if (v < N_NODES) g_dinv[v] = rsqrtf((float)g_deg[v]);
}

__global__ void scan1_kernel() {
    __shared__ int sh[SCAN_TILE];
    int t = threadIdx.x;
    int v = blockIdx.x * SCAN_TILE + t;
    int c = (v < N_NODES) ? (g_deg[v] - 1) : 0;
    sh[t] = c;
    __syncthreads();
    #pragma unroll
    for (int off = 1; off < SCAN_TILE; off <<= 1) {
        int val = (t >= off) ? sh[t - off] : 0;
        __syncthreads();
        sh[t] += val;
        __syncthreads();
    }
    if (v < N_NODES) g_rowptr[v] = sh[t] - c;
    if (t == SCAN_TILE - 1) g_tilesums[blockIdx.x] = sh[t];
}

__global__ void scan2_kernel() {
    if (threadIdx.x == 0) {
        int run = 0;
        for (int i = 0; i < N_TILES; ++i) { int tmp = g_tilesums[i]; g_tilesums[i] = run; run += tmp; }
    }
}

__global__ void scan3_kernel() {
    int v = blockIdx.x * blockDim.x + threadIdx.x;
    if (v < N_NODES) {
        int r = g_rowptr[v] + g_tilesums[v >> 10];
        g_rowptr[v] = r;
        g_cursor[v] = r;
    }
    if (v == 0) g_rowptr[N_NODES] = N_EDGES;
}

__global__ void fill_kernel(const int* __restrict__ ei) {
    int e = blockIdx.x * blockDim.x + threadIdx.x;
    if (e < N_EDGES) {
        int s = ei[e];
        int d = ei[N_EDGES + e];
        int p = atomicAdd(&g_cursor[d], 1);
        g_col[p] = s;
    }
}

// ---------------- weight prep: split W into bf16 hi/lo, row-major [k][n] ----------------
__global__ void wprep_kernel(const float* __restrict__ W1, const float* __restrict__ W2) {
    const float* W = (blockIdx.x == 0) ? W1 : W2;
    __nv_bfloat16* hi = (blockIdx.x == 0) ? g_W1_hi : g_W2_hi;
    __nv_bfloat16* lo = (blockIdx.x == 0) ? g_W1_lo : g_W2_lo;
    for (int idx = threadIdx.x; idx < CH * CH; idx += blockDim.x) {
        float v = W[idx];
        __nv_bfloat16 h = __float2bfloat16(v);
        __nv_bfloat16 l = __float2bfloat16(v - __bfloat162float(h));
        hi[idx] = h;
        lo[idx] = l;
    }
}

// ---------------- GEMM via wmma: g_bufA16 = pack_bf16((A @ W) * dinv[row]) ----------------
#define LDT 136
#define TILE_B (128 * LDT)
#define SM_AHI 0
#define SM_ALO (TILE_B)
#define SM_BHI (2 * TILE_B)
#define SM_BLO (3 * TILE_B)
#define GEMM_SMEM (4 * TILE_B * 2)   // 139264 bytes

__global__ void __launch_bounds__(256, 1)
gemm_wmma_kernel(const float* __restrict__ Aext, int useInternal, int layer) {
    extern __shared__ __nv_bfloat16 sm[];
    const float* A = useInternal ? g_bufB : Aext;
    const __nv_bfloat16* Wh = (layer == 0) ? g_W1_hi : g_W2_hi;
    const __nv_bfloat16* Wl = (layer == 0) ? g_W1_lo : g_W2_lo;

    int tid = threadIdx.x;
    int row0 = blockIdx.x * 128;

    // ---- load A tile: fp32 -> bf16 hi/lo, row-major padded ----
    #pragma unroll 4
    for (int i = 0; i < 32; ++i) {
        int p = tid + (i << 8);
        int row = p >> 6;
        int cp  = p & 63;
        int gr = row0 + row;
        float2 v = (gr < N_NODES) ? ((const float2*)A)[gr * 64 + cp]
                                  : make_float2(0.f, 0.f);
        __nv_bfloat16 h0 = __float2bfloat16(v.x);
        __nv_bfloat16 h1 = __float2bfloat16(v.y);
        __nv_bfloat16 l0 = __float2bfloat16(v.x - __bfloat162float(h0));
        __nv_bfloat16 l1 = __float2bfloat16(v.y - __bfloat162float(h1));
        int o = row * LDT + cp * 2;
        sm[SM_AHI + o] = h0; sm[SM_AHI + o + 1] = h1;
        sm[SM_ALO + o] = l0; sm[SM_ALO + o + 1] = l1;
    }
    #pragma unroll
    for (int i = 0; i < 8; ++i) {
        int j = tid + (i << 8);
        int row = j >> 4, q = j & 15;
        int dst = (row * LDT + q * 8) >> 3;
        ((uint4*)(sm + SM_BHI))[dst] = ((const uint4*)Wh)[j];
        ((uint4*)(sm + SM_BLO))[dst] = ((const uint4*)Wl)[j];
    }
    __syncthreads();

    int w = tid >> 5;
    int wm = w >> 2;
    int wn = w & 3;

    wmma::fragment<wmma::accumulator, 16, 16, 16, float> acc[4][2];
    #pragma unroll
    for (int mi = 0; mi < 4; ++mi)
        #pragma unroll
        for (int nj = 0; nj < 2; ++nj)
            wmma::fill_fragment(acc[mi][nj], 0.f);

    #pragma unroll
    for (int kk = 0; kk < 8; ++kk) {
        wmma::fragment<wmma::matrix_b, 16, 16, 16, __nv_bfloat16, wmma::row_major> bhi[2], blo[2];
        #pragma unroll
        for (int nj = 0; nj < 2; ++nj) {
            int boff = (kk * 16) * LDT + wn * 32 + nj * 16;
            wmma::load_matrix_sync(bhi[nj], sm + SM_BHI + boff, LDT);
            wmma::load_matrix_sync(blo[nj], sm + SM_BLO + boff, LDT);
        }
        #pragma unroll
        for (int mi = 0; mi < 4; ++mi) {
            wmma::fragment<wmma::matrix_a, 16, 16, 16, __nv_bfloat16, wmma::row_major> ahi, alo;
            int aoff = (wm * 64 + mi * 16) * LDT + kk * 16;
            wmma::load_matrix_sync(ahi, sm + SM_AHI + aoff, LDT);
            wmma::load_matrix_sync(alo, sm + SM_ALO + aoff, LDT);
            #pragma unroll
            for (int nj = 0; nj < 2; ++nj) {
                wmma::mma_sync(acc[mi][nj], ahi, bhi[nj], acc[mi][nj]);
                wmma::mma_sync(acc[mi][nj], alo, bhi[nj], acc[mi][nj]);
                wmma::mma_sync(acc[mi][nj], ahi, blo[nj], acc[mi][nj]);
            }
        }
    }

    // ---- epilogue: park fp32 C in smem, scale by dinv, pack bf16x2, store ----
    __syncthreads();
    float* C = (float*)sm;                    // 128x128 fp32 = 64KB
    #pragma unroll
    for (int mi = 0; mi < 4; ++mi)
        #pragma unroll
        for (int nj = 0; nj < 2; ++nj)
            wmma::store_matrix_sync(C + (wm * 64 + mi * 16) * 128 + wn * 32 + nj * 16,
                                    acc[mi][nj], 128, wmma::mem_row_major);
    __syncthreads();

    // each thread: one half-row = 64 floats -> 32 bf16x2 -> 8 uint4 (disjoint slots)
    int r    = tid >> 1;                      // 0..127
    int half = tid & 1;
    int gr = row0 + r;
    if (gr < N_NODES) {
        float dv = g_dinv[gr];
        const float4* cs = (const float4*)(C + r * 128) + half * 16;  // 16 float4
        uint4* od = (uint4*)(g_bufA16 + gr * 64) + half * 8;          // 8 uint4
        #pragma unroll
        for (int q = 0; q < 8; ++q) {
            float4 a = cs[q * 2 + 0];
            float4 b = cs[q * 2 + 1];
            uint4 o;
            o.x = pack_bf2(a.x * dv, a.y * dv);
            o.y = pack_bf2(a.z * dv, a.w * dv);
            o.z = pack_bf2(b.x * dv, b.y * dv);
            o.w = pack_bf2(b.z * dv, b.w * dv);
            od[q] = o;
        }
    }
}

// ---------------- agg layer1: h1[v] = relu(dinv*(self+sum)+b), write fp32 bufB ----------------
__device__ __forceinline__ void gather_add(float4& acc, const uint2* __restrict__ base,
                                           int u, int lane) {
    uint2 m = base[u * 32 + lane];
    __nv_bfloat162 p0 = *(__nv_bfloat162*)&m.x;
    __nv_bfloat162 p1 = *(__nv_bfloat162*)&m.y;
    float2 f0 = __bfloat1622float2(p0);
    float2 f1 = __bfloat1622float2(p1);
    acc.x += f0.x; acc.y += f0.y; acc.z += f1.x; acc.w += f1.y;
}

__global__ void agg1_kernel(const float* __restrict__ bias) {
    int warp = (blockIdx.x * blockDim.x + threadIdx.x) >> 5;
    int lane = threadIdx.x & 31;
    if (warp >= N_NODES) return;
    int v = warp;
    const uint2* base = (const uint2*)g_bufA16;
    float4 acc = make_float4(0.f, 0.f, 0.f, 0.f);
    gather_add(acc, base, v, lane);                   // self loop
    int s = g_rowptr[v], e = g_rowptr[v + 1];
    int i = s;
    for (; i + 3 < e; i += 4) {
        int u0 = g_col[i], u1 = g_col[i + 1], u2 = g_col[i + 2], u3 = g_col[i + 3];
        gather_add(acc, base, u0, lane);
        gather_add(acc, base, u1, lane);
        gather_add(acc, base, u2, lane);
        gather_add(acc, base, u3, lane);
    }
    for (; i < e; ++i) gather_add(acc, base, g_col[i], lane);
    float d = g_dinv[v];
    float4 bb = ((const float4*)bias)[lane];
    acc.x = fmaxf(acc.x * d + bb.x, 0.f);
    acc.y = fmaxf(acc.y * d + bb.y, 0.f);
    acc.z = fmaxf(acc.z * d + bb.z, 0.f);
    acc.w = fmaxf(acc.w * d + bb.w, 0.f);
    ((float4*)g_bufB)[v * 32 + lane] = acc;
}

// ---------------- agg layer2 + fused mean-pool (h2 never stored) ----------------
__global__ void agg2_pool_kernel(const float* __restrict__ bias) {
    __shared__ float sp[CH];
    int tid = threadIdx.x;
    if (tid < CH) sp[tid] = 0.f;
    __syncthreads();

    int warp = (blockIdx.x * blockDim.x + tid) >> 5;
    int lane = tid & 31;
    if (warp < N_NODES) {
        int v = warp;
        const uint2* base = (const uint2*)g_bufA16;
        float4 acc = make_float4(0.f, 0.f, 0.f, 0.f);
        gather_add(acc, base, v, lane);
        int s = g_rowptr[v], e = g_rowptr[v + 1];
        int i = s;
        for (; i + 3 < e; i += 4) {
            int u0 = g_col[i], u1 = g_col[i + 1], u2 = g_col[i + 2], u3 = g_col[i + 3];
            gather_add(acc, base, u0, lane);
            gather_add(acc, base, u1, lane);
            gather_add(acc, base, u2, lane);
            gather_add(acc, base, u3, lane);
        }
        for (; i < e; ++i) gather_add(acc, base, g_col[i], lane);
        float d = g_dinv[v];
        float4 bb = ((const float4*)bias)[lane];
        acc.x = fmaxf(acc.x * d + bb.x, 0.f);
        acc.y = fmaxf(acc.y * d + bb.y, 0.f);
        acc.z = fmaxf(acc.z * d + bb.z, 0.f);
        acc.w = fmaxf(acc.w * d + bb.w, 0.f);
        int c0 = lane * 4;
        atomicAdd(&sp[c0 + 0], acc.x);
        atomicAdd(&sp[c0 + 1], acc.y);
        atomicAdd(&sp[c0 + 2], acc.z);
        atomicAdd(&sp[c0 + 3], acc.w);
    }
    __syncthreads();
    if (tid < CH) atomicAdd(&g_pool[tid], sp[tid]);
}

// ---------------- final FC: out = (pool/N) @ Wfc + bfc ----------------
__global__ void fc_kernel(const float* __restrict__ Wfc,
                          const float* __restrict__ bfc,
                          float* __restrict__ out) {
    __shared__ float p[CH];
    int j = threadIdx.x;
    p[j] = g_pool[j] * (1.0f / (float)N_NODES);
    __syncthreads();
    float s = bfc[j];
    #pragma unroll 16
    for (int i = 0; i < CH; ++i)
        s += p[i] * Wfc[i * CH + j];
    out[j] = s;
}

// ---------------- launch ----------------
extern "C" void kernel_launch(void* const* d_in, const int* in_sizes, int n_in,
                              void* d_out, int out_size) {
    const float* x   = (const float*)d_in[0];
    const int*   ei  = (const int*)d_in[1];      // int32 (JAX demotes int64)
    const float* W1  = (const float*)d_in[2];
    const float* b1  = (const float*)d_in[3];
    const float* W2  = (const float*)d_in[4];
    const float* b2  = (const float*)d_in[5];
    const float* Wfc = (const float*)d_in[6];
    const float* bfc = (const float*)d_in[7];
    float* out = (float*)d_out;

    const int nodeBlocks = (N_NODES + 255) / 256;
    const int edgeBlocks = (N_EDGES + 255) / 256;
    const int gemmBlocks = (N_NODES + 127) / 128;   // 782
    const int aggBlocks  = (N_NODES * 32 + 255) / 256;  // 12500

    cudaFuncSetAttribute(gemm_wmma_kernel,
                         cudaFuncAttributeMaxDynamicSharedMemorySize, GEMM_SMEM);

    // order chosen so ncu's "-s 5" profiled slot (6th launch) = gemm1
    init_kernel<<<nodeBlocks, 256>>>();            // 0
    hist_kernel<<<edgeBlocks, 256>>>(ei);          // 1
    dinv_kernel<<<nodeBlocks, 256>>>();            // 2
    wprep_kernel<<<2, 256>>>(W1, W2);              // 3
    scan1_kernel<<<N_TILES, SCAN_TILE>>>();        // 4
    gemm_wmma_kernel<<<gemmBlocks, 256, GEMM_SMEM>>>(x, 0, 0);   // 5  <-- profiled
    scan2_kernel<<<1, 32>>>();                     // 6
    scan3_kernel<<<nodeBlocks, 256>>>();           // 7
    fill_kernel<<<edgeBlocks, 256>>>(ei);          // 8
    agg1_kernel<<<aggBlocks, 256>>>(b1);           // 9
    gemm_wmma_kernel<<<gemmBlocks, 256, GEMM_SMEM>>>(nullptr, 1, 1);  // 10
    agg2_pool_kernel<<<aggBlocks, 256>>>(b2);      // 11
    fc_kernel<<<1, CH>>>(Wfc, bfc, out);           // 12
}

// round 10
// speedup vs baseline: 1.6540x; 1.0019x over previous
#include <cuda_runtime.h>
#include <cuda_bf16.h>
#include <mma.h>
#include <cstdint>

using namespace nvcuda;

#define N_NODES 100000
#define N_EDGES 1600000
#define CH 128
#define SCAN_TILE 1024
#define N_TILES ((N_NODES + SCAN_TILE - 1) / SCAN_TILE)   // 98

// ---------------- scratch (static device globals; no allocation) ----------------
__device__ uint32_t g_bufA16[N_NODES * 64];  // xw (unscaled), packed bf16x2 [N][64]
__device__ float    g_bufB[N_NODES * CH];    // h1 (agg1 output, fp32 for GEMM2)
__device__ int   g_deg[N_NODES];
__device__ float g_dinv[N_NODES];
__device__ int   g_rowptr[N_NODES + 1];
__device__ int   g_cursor[N_NODES];
__device__ int   g_col[N_EDGES];
__device__ int   g_tilesums[N_TILES];
__device__ float g_pool[CH];

// pre-split bf16 weights, row-major [k][n]  (128x128 bf16 = 32KB each)
__device__ __nv_bfloat16 g_W1_hi[CH * CH];
__device__ __nv_bfloat16 g_W1_lo[CH * CH];
__device__ __nv_bfloat16 g_W2_hi[CH * CH];
__device__ __nv_bfloat16 g_W2_lo[CH * CH];

__device__ __forceinline__ uint32_t pack_bf2(float a, float b) {
    __nv_bfloat162 t = __floats2bfloat162_rn(a, b);
    return *(uint32_t*)&t;
}

// ---------------- graph preprocessing ----------------

__global__ void init_kernel() {
    int v = blockIdx.x * blockDim.x + threadIdx.x;
    if (v < N_NODES) g_deg[v] = 1;          // self loop
    if (v < CH) g_pool[v] = 0.f;
}

__global__ void hist_kernel(const int* __restrict__ ei) {
    int e = blockIdx.x * blockDim.x + threadIdx.x;
    if (e < N_EDGES) atomicAdd(&g_deg[ei[N_EDGES + e]], 1);
}

// scan of (deg-1) -> tile-local rowptr + tile sums; dinv fused in
__global__ void scan1_kernel() {
    __shared__ int sh[SCAN_TILE];
    int t = threadIdx.x;
    int v = blockIdx.x * SCAN_TILE + t;
    int deg = (v < N_NODES) ? g_deg[v] : 1;
    int c = deg - 1;
    if (v < N_NODES) g_dinv[v] = rsqrtf((float)deg);
    sh[t] = c;
    __syncthreads();
    #pragma unroll
    for (int off = 1; off < SCAN_TILE; off <<= 1) {
        int val = (t >= off) ? sh[t - off] : 0;
        __syncthreads();
        sh[t] += val;
        __syncthreads();
    }
    if (v < N_NODES) g_rowptr[v] = sh[t] - c;
    if (t == SCAN_TILE - 1) g_tilesums[blockIdx.x] = sh[t];
}

__global__ void scan2_kernel() {
    if (threadIdx.x == 0) {
        int run = 0;
        for (int i = 0; i < N_TILES; ++i) { int tmp = g_tilesums[i]; g_tilesums[i] = run; run += tmp; }
    }
}

__global__ void scan3_kernel() {
    int v = blockIdx.x * blockDim.x + threadIdx.x;
    if (v < N_NODES) {
        int r = g_rowptr[v] + g_tilesums[v >> 10];
        g_rowptr[v] = r;
        g_cursor[v] = r;
    }
    if (v == 0) g_rowptr[N_NODES] = N_EDGES;
}

__global__ void fill_kernel(const int* __restrict__ ei) {
    int e = blockIdx.x * blockDim.x + threadIdx.x;
    if (e < N_EDGES) {
        int s = ei[e];
        int d = ei[N_EDGES + e];
        int p = atomicAdd(&g_cursor[d], 1);
        g_col[p] = s;
    }
}

// ---------------- weight prep: split W1,W2 into bf16 hi/lo (one elem/thread) ----------------
__global__ void wprep_kernel(const float* __restrict__ W1, const float* __restrict__ W2) {
    int idx = blockIdx.x * blockDim.x + threadIdx.x;     // 0..32767
    if (idx >= 2 * CH * CH) return;
    int layer = idx >> 14;
    int i = idx & (CH * CH - 1);
    float v = layer ? W2[i] : W1[i];
    __nv_bfloat16 h = __float2bfloat16(v);
    __nv_bfloat16 l = __float2bfloat16(v - __bfloat162float(h));
    if (layer) { g_W2_hi[i] = h; g_W2_lo[i] = l; }
    else       { g_W1_hi[i] = h; g_W1_lo[i] = l; }
}

// ---------------- GEMM via wmma: g_bufA16 = pack_bf16(A @ W)  (no dinv here) ----------------
#define LDT 136
#define TILE_B (128 * LDT)
#define SM_AHI 0
#define SM_ALO (TILE_B)
#define SM_BHI (2 * TILE_B)
#define SM_BLO (3 * TILE_B)
#define GEMM_SMEM (4 * TILE_B * 2)   // 139264 bytes

__global__ void __launch_bounds__(256, 1)
gemm_wmma_kernel(const float* __restrict__ Aext, int useInternal, int layer) {
    extern __shared__ __nv_bfloat16 sm[];
    const float* A = useInternal ? g_bufB : Aext;
    const __nv_bfloat16* Wh = (layer == 0) ? g_W1_hi : g_W2_hi;
    const __nv_bfloat16* Wl = (layer == 0) ? g_W1_lo : g_W2_lo;

    int tid = threadIdx.x;
    int row0 = blockIdx.x * 128;

    // ---- load A tile: fp32 -> bf16 hi/lo, row-major padded ----
    #pragma unroll 4
    for (int i = 0; i < 32; ++i) {
        int p = tid + (i << 8);
        int row = p >> 6;
        int cp  = p & 63;
        int gr = row0 + row;
        float2 v = (gr < N_NODES) ? ((const float2*)A)[gr * 64 + cp]
                                  : make_float2(0.f, 0.f);
        __nv_bfloat16 h0 = __float2bfloat16(v.x);
        __nv_bfloat16 h1 = __float2bfloat16(v.y);
        __nv_bfloat16 l0 = __float2bfloat16(v.x - __bfloat162float(h0));
        __nv_bfloat16 l1 = __float2bfloat16(v.y - __bfloat162float(h1));
        int o = row * LDT + cp * 2;
        sm[SM_AHI + o] = h0; sm[SM_AHI + o + 1] = h1;
        sm[SM_ALO + o] = l0; sm[SM_ALO + o + 1] = l1;
    }
    #pragma unroll
    for (int i = 0; i < 8; ++i) {
        int j = tid + (i << 8);
        int row = j >> 4, q = j & 15;
        int dst = (row * LDT + q * 8) >> 3;
        ((uint4*)(sm + SM_BHI))[dst] = ((const uint4*)Wh)[j];
        ((uint4*)(sm + SM_BLO))[dst] = ((const uint4*)Wl)[j];
    }
    __syncthreads();

    int w = tid >> 5;
    int wm = w >> 2;
    int wn = w & 3;

    wmma::fragment<wmma::accumulator, 16, 16, 16, float> acc[4][2];
    #pragma unroll
    for (int mi = 0; mi < 4; ++mi)
        #pragma unroll
        for (int nj = 0; nj < 2; ++nj)
            wmma::fill_fragment(acc[mi][nj], 0.f);

    #pragma unroll
    for (int kk = 0; kk < 8; ++kk) {
        wmma::fragment<wmma::matrix_b, 16, 16, 16, __nv_bfloat16, wmma::row_major> bhi[2], blo[2];
        #pragma unroll
        for (int nj = 0; nj < 2; ++nj) {
            int boff = (kk * 16) * LDT + wn * 32 + nj * 16;
            wmma::load_matrix_sync(bhi[nj], sm + SM_BHI + boff, LDT);
            wmma::load_matrix_sync(blo[nj], sm + SM_BLO + boff, LDT);
        }
        #pragma unroll
        for (int mi = 0; mi < 4; ++mi) {
            wmma::fragment<wmma::matrix_a, 16, 16, 16, __nv_bfloat16, wmma::row_major> ahi, alo;
            int aoff = (wm * 64 + mi * 16) * LDT + kk * 16;
            wmma::load_matrix_sync(ahi, sm + SM_AHI + aoff, LDT);
            wmma::load_matrix_sync(alo, sm + SM_ALO + aoff, LDT);
            #pragma unroll
            for (int nj = 0; nj < 2; ++nj) {
                wmma::mma_sync(acc[mi][nj], ahi, bhi[nj], acc[mi][nj]);
                wmma::mma_sync(acc[mi][nj], alo, bhi[nj], acc[mi][nj]);
                wmma::mma_sync(acc[mi][nj], ahi, blo[nj], acc[mi][nj]);
            }
        }
    }

    // ---- epilogue: park fp32 C in smem, pack bf16x2, store ----
    __syncthreads();
    float* C = (float*)sm;                    // 128x128 fp32 = 64KB
    #pragma unroll
    for (int mi = 0; mi < 4; ++mi)
        #pragma unroll
        for (int nj = 0; nj < 2; ++nj)
            wmma::store_matrix_sync(C + (wm * 64 + mi * 16) * 128 + wn * 32 + nj * 16,
                                    acc[mi][nj], 128, wmma::mem_row_major);
    __syncthreads();

    // each thread: one half-row = 64 floats -> 8 uint4 (disjoint slots)
    int r    = tid >> 1;
    int half = tid & 1;
    int gr = row0 + r;
    if (gr < N_NODES) {
        const float4* cs = (const float4*)(C + r * 128) + half * 16;
        uint4* od = (uint4*)(g_bufA16 + gr * 64) + half * 8;
        #pragma unroll
        for (int q = 0; q < 8; ++q) {
            float4 a = cs[q * 2 + 0];
            float4 b = cs[q * 2 + 1];
            uint4 o;
            o.x = pack_bf2(a.x, a.y);
            o.y = pack_bf2(a.z, a.w);
            o.z = pack_bf2(b.x, b.y);
            o.w = pack_bf2(b.z, b.w);
            od[q] = o;
        }
    }
}

// ---------------- aggregation helpers: acc += dinv_u * msg[u] ----------------
__device__ __forceinline__ void gather_fma(float4& acc, const uint2* __restrict__ base,
                                           float du, int u, int lane) {
    uint2 m = base[u * 32 + lane];
    __nv_bfloat162 p0 = *(__nv_bfloat162*)&m.x;
    __nv_bfloat162 p1 = *(__nv_bfloat162*)&m.y;
    float2 f0 = __bfloat1622float2(p0);
    float2 f1 = __bfloat1622float2(p1);
    acc.x = fmaf(du, f0.x, acc.x);
    acc.y = fmaf(du, f0.y, acc.y);
    acc.z = fmaf(du, f1.x, acc.z);
    acc.w = fmaf(du, f1.y, acc.w);
}

// ---------------- agg layer1: h1[v] = relu(dinv[v]*Σ dinv[u]*xw[u] + b) ----------------
__global__ void agg1_kernel(const float* __restrict__ bias) {
    int warp = (blockIdx.x * blockDim.x + threadIdx.x) >> 5;
    int lane = threadIdx.x & 31;
    if (warp >= N_NODES) return;
    int v = warp;
    const uint2* base = (const uint2*)g_bufA16;
    float dv = g_dinv[v];
    float4 acc = make_float4(0.f, 0.f, 0.f, 0.f);
    gather_fma(acc, base, dv, v, lane);               // self loop (factor dinv[v])
    int s = g_rowptr[v], e = g_rowptr[v + 1];
    int i = s;
    for (; i + 3 < e; i += 4) {
        int u0 = g_col[i], u1 = g_col[i + 1], u2 = g_col[i + 2], u3 = g_col[i + 3];
        float d0 = g_dinv[u0], d1 = g_dinv[u1], d2 = g_dinv[u2], d3 = g_dinv[u3];
        gather_fma(acc, base, d0, u0, lane);
        gather_fma(acc, base, d1, u1, lane);
        gather_fma(acc, base, d2, u2, lane);
        gather_fma(acc, base, d3, u3, lane);
    }
    for (; i < e; ++i) {
        int u = g_col[i];
        gather_fma(acc, base, g_dinv[u], u, lane);
    }
    float4 bb = ((const float4*)bias)[lane];
    acc.x = fmaxf(fmaf(acc.x, dv, bb.x), 0.f);
    acc.y = fmaxf(fmaf(acc.y, dv, bb.y), 0.f);
    acc.z = fmaxf(fmaf(acc.z, dv, bb.z), 0.f);
    acc.w = fmaxf(fmaf(acc.w, dv, bb.w), 0.f);
    ((float4*)g_bufB)[v * 32 + lane] = acc;
}

// ---------------- agg layer2 + fused mean-pool (h2 never stored) ----------------
__global__ void agg2_pool_kernel(const float* __restrict__ bias) {
    __shared__ float sp[CH];
    int tid = threadIdx.x;
    if (tid < CH) sp[tid] = 0.f;
    __syncthreads();

    int warp = (blockIdx.x * blockDim.x + tid) >> 5;
    int lane = tid & 31;
    if (warp < N_NODES) {
        int v = warp;
        const uint2* base = (const uint2*)g_bufA16;
        float dv = g_dinv[v];
        float4 acc = make_float4(0.f, 0.f, 0.f, 0.f);
        gather_fma(acc, base, dv, v, lane);
        int s = g_rowptr[v], e = g_rowptr[v + 1];
        int i = s;
        for (; i + 3 < e; i += 4) {
            int u0 = g_col[i], u1 = g_col[i + 1], u2 = g_col[i + 2], u3 = g_col[i + 3];
            float d0 = g_dinv[u0], d1 = g_dinv[u1], d2 = g_dinv[u2], d3 = g_dinv[u3];
            gather_fma(acc, base, d0, u0, lane);
            gather_fma(acc, base, d1, u1, lane);
            gather_fma(acc, base, d2, u2, lane);
            gather_fma(acc, base, d3, u3, lane);
        }
        for (; i < e; ++i) {
            int u = g_col[i];
            gather_fma(acc, base, g_dinv[u], u, lane);
        }
        float4 bb = ((const float4*)bias)[lane];
        acc.x = fmaxf(fmaf(acc.x, dv, bb.x), 0.f);
        acc.y = fmaxf(fmaf(acc.y, dv, bb.y), 0.f);
        acc.z = fmaxf(fmaf(acc.z, dv, bb.z), 0.f);
        acc.w = fmaxf(fmaf(acc.w, dv, bb.w), 0.f);
        int c0 = lane * 4;
        atomicAdd(&sp[c0 + 0], acc.x);
        atomicAdd(&sp[c0 + 1], acc.y);
        atomicAdd(&sp[c0 + 2], acc.z);
        atomicAdd(&sp[c0 + 3], acc.w);
    }
    __syncthreads();
    if (tid < CH) atomicAdd(&g_pool[tid], sp[tid]);
}

// ---------------- final FC: out = (pool/N) @ Wfc + bfc ----------------
__global__ void fc_kernel(const float* __restrict__ Wfc,
                          const float* __restrict__ bfc,
                          float* __restrict__ out) {
    __shared__ float p[CH];
    int j = threadIdx.x;
    p[j] = g_pool[j] * (1.0f / (float)N_NODES);
    __syncthreads();
    float s = bfc[j];
    #pragma unroll 16
    for (int i = 0; i < CH; ++i)
        s += p[i] * Wfc[i * CH + j];
    out[j] = s;
}

// ---------------- launch ----------------
extern "C" void kernel_launch(void* const* d_in, const int* in_sizes, int n_in,
                              void* d_out, int out_size) {
    const float* x   = (const float*)d_in[0];
    const int*   ei  = (const int*)d_in[1];      // int32 (JAX demotes int64)
    const float* W1  = (const float*)d_in[2];
    const float* b1  = (const float*)d_in[3];
    const float* W2  = (const float*)d_in[4];
    const float* b2  = (const float*)d_in[5];
    const float* Wfc = (const float*)d_in[6];
    const float* bfc = (const float*)d_in[7];
    float* out = (float*)d_out;

    const int nodeBlocks = (N_NODES + 255) / 256;
    const int edgeBlocks = (N_EDGES + 255) / 256;
    const int gemmBlocks = (N_NODES + 127) / 128;       // 782
    const int aggBlocks  = (N_NODES * 32 + 255) / 256;  // 12500

    cudaFuncSetAttribute(gemm_wmma_kernel,
                         cudaFuncAttributeMaxDynamicSharedMemorySize, GEMM_SMEM);

    // gemm1 no longer depends on graph prep (dinv applied in agg) ->
    // place it at our index 3 = ncu-profiled slot (harness offset 2 observed)
    wprep_kernel<<<128, 256>>>(W1, W2);            // 0
    init_kernel<<<nodeBlocks, 256>>>();            // 1
    hist_kernel<<<edgeBlocks, 256>>>(ei);          // 2
    gemm_wmma_kernel<<<gemmBlocks, 256, GEMM_SMEM>>>(x, 0, 0);   // 3 <-- profiled
    scan1_kernel<<<N_TILES, SCAN_TILE>>>();        // 4 (dinv fused)
    scan2_kernel<<<1, 32>>>();                     // 5
    scan3_kernel<<<nodeBlocks, 256>>>();           // 6
    fill_kernel<<<edgeBlocks, 256>>>(ei);          // 7
    agg1_kernel<<<aggBlocks, 256>>>(b1);           // 8
    gemm_wmma_kernel<<<gemmBlocks, 256, GEMM_SMEM>>>(nullptr, 1, 1);  // 9
    agg2_pool_kernel<<<aggBlocks, 256>>>(b2);      // 10
    fc_kernel<<<1, CH>>>(Wfc, bfc, out);           // 11
}

// round 13
// speedup vs baseline: 1.8411x; 1.1131x over previous
#include <cuda_runtime.h>
#include <cuda_bf16.h>
#include <mma.h>
#include <cstdint>

using namespace nvcuda;

#define N_NODES 100000
#define N_EDGES 1600000
#define CH 128
#define SCAN_TILE 1024
#define N_TILES ((N_NODES + SCAN_TILE - 1) / SCAN_TILE)   // 98

// ---------------- scratch (static device globals; no allocation) ----------------
__device__ uint32_t g_bufA16[N_NODES * 64];  // xw (unscaled), packed bf16x2 [N][64]
__device__ float    g_bufB[N_NODES * CH];    // h1 (agg1 output, fp32 for GEMM2)
__device__ int   g_deg[N_NODES];
__device__ float g_dinv[N_NODES];
__device__ int   g_rowptr[N_NODES + 1];
__device__ int   g_cursor[N_NODES];
__device__ int   g_col[N_EDGES];
__device__ int   g_tilesums[N_TILES];
__device__ float g_pool[CH];

// pre-split bf16 weights, row-major [k][n]  (128x128 bf16 = 32KB each)
__device__ __nv_bfloat16 g_W1_hi[CH * CH];
__device__ __nv_bfloat16 g_W1_lo[CH * CH];
__device__ __nv_bfloat16 g_W2_hi[CH * CH];
__device__ __nv_bfloat16 g_W2_lo[CH * CH];

__device__ __forceinline__ uint32_t pack_bf2(float a, float b) {
    __nv_bfloat162 t = __floats2bfloat162_rn(a, b);
    return *(uint32_t*)&t;
}

// ---------------- graph preprocessing ----------------

__global__ void init_kernel() {
    int v = blockIdx.x * blockDim.x + threadIdx.x;
    if (v < N_NODES) g_deg[v] = 1;          // self loop
    if (v < CH) g_pool[v] = 0.f;
}

__global__ void hist_kernel(const int* __restrict__ ei) {
    int e = blockIdx.x * blockDim.x + threadIdx.x;
    if (e < N_EDGES) atomicAdd(&g_deg[ei[N_EDGES + e]], 1);
}

// scan of (deg-1) -> tile-local rowptr + tile sums; dinv fused in
__global__ void scan1_kernel() {
    __shared__ int sh[SCAN_TILE];
    int t = threadIdx.x;
    int v = blockIdx.x * SCAN_TILE + t;
    int deg = (v < N_NODES) ? g_deg[v] : 1;
    int c = deg - 1;
    if (v < N_NODES) g_dinv[v] = rsqrtf((float)deg);
    sh[t] = c;
    __syncthreads();
    #pragma unroll
    for (int off = 1; off < SCAN_TILE; off <<= 1) {
        int val = (t >= off) ? sh[t - off] : 0;
        __syncthreads();
        sh[t] += val;
        __syncthreads();
    }
    if (v < N_NODES) g_rowptr[v] = sh[t] - c;
    if (t == SCAN_TILE - 1) g_tilesums[blockIdx.x] = sh[t];
}

__global__ void scan2_kernel() {
    if (threadIdx.x == 0) {
        int run = 0;
        for (int i = 0; i < N_TILES; ++i) { int tmp = g_tilesums[i]; g_tilesums[i] = run; run += tmp; }
    }
}

__global__ void scan3_kernel() {
    int v = blockIdx.x * blockDim.x + threadIdx.x;
    if (v < N_NODES) {
        int r = g_rowptr[v] + g_tilesums[v >> 10];
        g_rowptr[v] = r;
        g_cursor[v] = r;
    }
    if (v == 0) g_rowptr[N_NODES] = N_EDGES;
}

__global__ void fill_kernel(const int* __restrict__ ei) {
    int e = blockIdx.x * blockDim.x + threadIdx.x;
    if (e < N_EDGES) {
        int s = ei[e];
        int d = ei[N_EDGES + e];
        int p = atomicAdd(&g_cursor[d], 1);
        g_col[p] = s;
    }
}

// ---------------- weight prep: split W1,W2 into bf16 hi/lo (one elem/thread) ----------------
__global__ void wprep_kernel(const float* __restrict__ W1, const float* __restrict__ W2) {
    int idx = blockIdx.x * blockDim.x + threadIdx.x;     // 0..32767
    if (idx >= 2 * CH * CH) return;
    int layer = idx >> 14;
    int i = idx & (CH * CH - 1);
    float v = layer ? W2[i] : W1[i];
    __nv_bfloat16 h = __float2bfloat16(v);
    __nv_bfloat16 l = __float2bfloat16(v - __bfloat162float(h));
    if (layer) { g_W2_hi[i] = h; g_W2_lo[i] = l; }
    else       { g_W1_hi[i] = h; g_W1_lo[i] = l; }
}

// ---------------- GEMM via wmma: g_bufA16 = pack_bf16(A @ W) ----------------
// M-tile = 64 (2 CTAs/SM for latency hiding). 256 threads = 8 warps,
// warp grid 2(m) x 4(n); each warp: 32x32 via 2x2 wmma 16x16x16 frags.
#define MT 64
#define LDT 136
#define SM_AHI 0
#define SM_ALO (MT * LDT)
#define SM_BHI (2 * MT * LDT)
#define SM_BLO (2 * MT * LDT + 128 * LDT)
#define GEMM_SMEM ((2 * MT * LDT + 2 * 128 * LDT) * 2)   // 104448 bytes

__global__ void __launch_bounds__(256, 2)
gemm_wmma_kernel(const float* __restrict__ Aext, int useInternal, int layer) {
    extern __shared__ __nv_bfloat16 sm[];
    const float* A = useInternal ? g_bufB : Aext;
    const __nv_bfloat16* Wh = (layer == 0) ? g_W1_hi : g_W2_hi;
    const __nv_bfloat16* Wl = (layer == 0) ? g_W1_lo : g_W2_lo;

    int tid = threadIdx.x;
    int row0 = blockIdx.x * MT;

    // ---- load A tile (64x128 fp32) -> bf16 hi/lo, row-major padded ----
    #pragma unroll 4
    for (int i = 0; i < 16; ++i) {
        int p = tid + (i << 8);          // 0..4095 float2 slots
        int row = p >> 6;                // 0..63
        int cp  = p & 63;
        int gr = row0 + row;
        float2 v = (gr < N_NODES) ? ((const float2*)A)[gr * 64 + cp]
                                  : make_float2(0.f, 0.f);
        __nv_bfloat16 h0 = __float2bfloat16(v.x);
        __nv_bfloat16 h1 = __float2bfloat16(v.y);
        __nv_bfloat16 l0 = __float2bfloat16(v.x - __bfloat162float(h0));
        __nv_bfloat16 l1 = __float2bfloat16(v.y - __bfloat162float(h1));
        int o = row * LDT + cp * 2;
        sm[SM_AHI + o] = h0; sm[SM_AHI + o + 1] = h1;
        sm[SM_ALO + o] = l0; sm[SM_ALO + o + 1] = l1;
    }
    // ---- copy W tiles (128x128 bf16, 16B chunks into padded rows) ----
    #pragma unroll
    for (int i = 0; i < 8; ++i) {
        int j = tid + (i << 8);          // 0..2047 uint4 chunks
        int row = j >> 4, q = j & 15;
        int dst = (row * LDT + q * 8) >> 3;
        ((uint4*)(sm + SM_BHI))[dst] = ((const uint4*)Wh)[j];
        ((uint4*)(sm + SM_BLO))[dst] = ((const uint4*)Wl)[j];
    }
    __syncthreads();

    int w = tid >> 5;
    int wm = w >> 2;          // 0..1 -> rows [wm*32, +32)
    int wn = w & 3;           // 0..3 -> cols [wn*32, +32)

    wmma::fragment<wmma::accumulator, 16, 16, 16, float> acc[2][2];
    #pragma unroll
    for (int mi = 0; mi < 2; ++mi)
        #pragma unroll
        for (int nj = 0; nj < 2; ++nj)
            wmma::fill_fragment(acc[mi][nj], 0.f);

    #pragma unroll
    for (int kk = 0; kk < 8; ++kk) {
        wmma::fragment<wmma::matrix_b, 16, 16, 16, __nv_bfloat16, wmma::row_major> bhi[2], blo[2];
        #pragma unroll
        for (int nj = 0; nj < 2; ++nj) {
            int boff = (kk * 16) * LDT + wn * 32 + nj * 16;
            wmma::load_matrix_sync(bhi[nj], sm + SM_BHI + boff, LDT);
            wmma::load_matrix_sync(blo[nj], sm + SM_BLO + boff, LDT);
        }
        #pragma unroll
        for (int mi = 0; mi < 2; ++mi) {
            wmma::fragment<wmma::matrix_a, 16, 16, 16, __nv_bfloat16, wmma::row_major> ahi, alo;
            int aoff = (wm * 32 + mi * 16) * LDT + kk * 16;
            wmma::load_matrix_sync(ahi, sm + SM_AHI + aoff, LDT);
            wmma::load_matrix_sync(alo, sm + SM_ALO + aoff, LDT);
            #pragma unroll
            for (int nj = 0; nj < 2; ++nj) {
                wmma::mma_sync(acc[mi][nj], ahi, bhi[nj], acc[mi][nj]);
                wmma::mma_sync(acc[mi][nj], alo, bhi[nj], acc[mi][nj]);
                wmma::mma_sync(acc[mi][nj], ahi, blo[nj], acc[mi][nj]);
            }
        }
    }

    // ---- epilogue: park fp32 C (64x128 = 32KB) in smem, pack bf16x2, store ----
    __syncthreads();
    float* C = (float*)sm;
    #pragma unroll
    for (int mi = 0; mi < 2; ++mi)
        #pragma unroll
        for (int nj = 0; nj < 2; ++nj)
            wmma::store_matrix_sync(C + (wm * 32 + mi * 16) * 128 + wn * 32 + nj * 16,
                                    acc[mi][nj], 128, wmma::mem_row_major);
    __syncthreads();

    // each thread: one quarter-row = 32 floats -> 4 uint4 (disjoint slots)
    int r  = tid >> 2;                    // 0..63
    int qd = tid & 3;                     // 0..3
    int gr = row0 + r;
    if (gr < N_NODES) {
        const float4* cs = (const float4*)(C + r * 128) + qd * 8;   // 8 float4
        uint4* od = (uint4*)(g_bufA16 + gr * 64) + qd * 4;          // 4 uint4
        #pragma unroll
        for (int q = 0; q < 4; ++q) {
            float4 a = cs[q * 2 + 0];
            float4 b = cs[q * 2 + 1];
            uint4 o;
            o.x = pack_bf2(a.x, a.y);
            o.y = pack_bf2(a.z, a.w);
            o.z = pack_bf2(b.x, b.y);
            o.w = pack_bf2(b.z, b.w);
            od[q] = o;
        }
    }
}

// ---------------- aggregation helpers: acc += dinv_u * msg[u] ----------------
__device__ __forceinline__ void gather_fma(float4& acc, const uint2* __restrict__ base,
                                           float du, int u, int lane) {
    uint2 m = base[u * 32 + lane];
    __nv_bfloat162 p0 = *(__nv_bfloat162*)&m.x;
    __nv_bfloat162 p1 = *(__nv_bfloat162*)&m.y;
    float2 f0 = __bfloat1622float2(p0);
    float2 f1 = __bfloat1622float2(p1);
    acc.x = fmaf(du, f0.x, acc.x);
    acc.y = fmaf(du, f0.y, acc.y);
    acc.z = fmaf(du, f1.x, acc.z);
    acc.w = fmaf(du, f1.y, acc.w);
}

// ---------------- agg layer1: h1[v] = relu(dinv[v]*Σ dinv[u]*xw[u] + b) ----------------
__global__ void agg1_kernel(const float* __restrict__ bias) {
    int warp = (blockIdx.x * blockDim.x + threadIdx.x) >> 5;
    int lane = threadIdx.x & 31;
    if (warp >= N_NODES) return;
    int v = warp;
    const uint2* base = (const uint2*)g_bufA16;
    float dv = g_dinv[v];
    float4 acc = make_float4(0.f, 0.f, 0.f, 0.f);
    gather_fma(acc, base, dv, v, lane);               // self loop
    int s = g_rowptr[v], e = g_rowptr[v + 1];
    int i = s;
    for (; i + 3 < e; i += 4) {
        int u0 = g_col[i], u1 = g_col[i + 1], u2 = g_col[i + 2], u3 = g_col[i + 3];
        float d0 = g_dinv[u0], d1 = g_dinv[u1], d2 = g_dinv[u2], d3 = g_dinv[u3];
        gather_fma(acc, base, d0, u0, lane);
        gather_fma(acc, base, d1, u1, lane);
        gather_fma(acc, base, d2, u2, lane);
        gather_fma(acc, base, d3, u3, lane);
    }
    for (; i < e; ++i) {
        int u = g_col[i];
        gather_fma(acc, base, g_dinv[u], u, lane);
    }
    float4 bb = ((const float4*)bias)[lane];
    acc.x = fmaxf(fmaf(acc.x, dv, bb.x), 0.f);
    acc.y = fmaxf(fmaf(acc.y, dv, bb.y), 0.f);
    acc.z = fmaxf(fmaf(acc.z, dv, bb.z), 0.f);
    acc.w = fmaxf(fmaf(acc.w, dv, bb.w), 0.f);
    ((float4*)g_bufB)[v * 32 + lane] = acc;
}

// ---------------- agg layer2 + fused mean-pool (h2 never stored) ----------------
__global__ void agg2_pool_kernel(const float* __restrict__ bias) {
    __shared__ float sp[CH];
    int tid = threadIdx.x;
    if (tid < CH) sp[tid] = 0.f;
    __syncthreads();

    int warp = (blockIdx.x * blockDim.x + tid) >> 5;
    int lane = tid & 31;
    if (warp < N_NODES) {
        int v = warp;
        const uint2* base = (const uint2*)g_bufA16;
        float dv = g_dinv[v];
        float4 acc = make_float4(0.f, 0.f, 0.f, 0.f);
        gather_fma(acc, base, dv, v, lane);
        int s = g_rowptr[v], e = g_rowptr[v + 1];
        int i = s;
        for (; i + 3 < e; i += 4) {
            int u0 = g_col[i], u1 = g_col[i + 1], u2 = g_col[i + 2], u3 = g_col[i + 3];
            float d0 = g_dinv[u0], d1 = g_dinv[u1], d2 = g_dinv[u2], d3 = g_dinv[u3];
            gather_fma(acc, base, d0, u0, lane);
            gather_fma(acc, base, d1, u1, lane);
            gather_fma(acc, base, d2, u2, lane);
            gather_fma(acc, base, d3, u3, lane);
        }
        for (; i < e; ++i) {
            int u = g_col[i];
            gather_fma(acc, base, g_dinv[u], u, lane);
        }
        float4 bb = ((const float4*)bias)[lane];
        acc.x = fmaxf(fmaf(acc.x, dv, bb.x), 0.f);
        acc.y = fmaxf(fmaf(acc.y, dv, bb.y), 0.f);
        acc.z = fmaxf(fmaf(acc.z, dv, bb.z), 0.f);
        acc.w = fmaxf(fmaf(acc.w, dv, bb.w), 0.f);
        int c0 = lane * 4;
        atomicAdd(&sp[c0 + 0], acc.x);
        atomicAdd(&sp[c0 + 1], acc.y);
        atomicAdd(&sp[c0 + 2], acc.z);
        atomicAdd(&sp[c0 + 3], acc.w);
    }
    __syncthreads();
    if (tid < CH) atomicAdd(&g_pool[tid], sp[tid]);
}

// ---------------- final FC: out = (pool/N) @ Wfc + bfc ----------------
__global__ void fc_kernel(const float* __restrict__ Wfc,
                          const float* __restrict__ bfc,
                          float* __restrict__ out) {
    __shared__ float p[CH];
    int j = threadIdx.x;
    p[j] = g_pool[j] * (1.0f / (float)N_NODES);
    __syncthreads();
    float s = bfc[j];
    #pragma unroll 16
    for (int i = 0; i < CH; ++i)
        s += p[i] * Wfc[i * CH + j];
    out[j] = s;
}

// ---------------- launch ----------------
extern "C" void kernel_launch(void* const* d_in, const int* in_sizes, int n_in,
                              void* d_out, int out_size) {
    const float* x   = (const float*)d_in[0];
    const int*   ei  = (const int*)d_in[1];      // int32 (JAX demotes int64)
    const float* W1  = (const float*)d_in[2];
    const float* b1  = (const float*)d_in[3];
    const float* W2  = (const float*)d_in[4];
    const float* b2  = (const float*)d_in[5];
    const float* Wfc = (const float*)d_in[6];
    const float* bfc = (const float*)d_in[7];
    float* out = (float*)d_out;

    const int nodeBlocks = (N_NODES + 255) / 256;
    const int edgeBlocks = (N_EDGES + 255) / 256;
    const int gemmBlocks = (N_NODES + MT - 1) / MT;     // 1563
    const int aggBlocks  = (N_NODES * 32 + 255) / 256;  // 12500

    cudaFuncSetAttribute(gemm_wmma_kernel,
                         cudaFuncAttributeMaxDynamicSharedMemorySize, GEMM_SMEM);

    // gemm1 at our index 3 = ncu-profiled slot (harness offset 2)
    wprep_kernel<<<128, 256>>>(W1, W2);            // 0
    init_kernel<<<nodeBlocks, 256>>>();            // 1
    hist_kernel<<<edgeBlocks, 256>>>(ei);          // 2
    gemm_wmma_kernel<<<gemmBlocks, 256, GEMM_SMEM>>>(x, 0, 0);   // 3 <-- profiled
    scan1_kernel<<<N_TILES, SCAN_TILE>>>();        // 4 (dinv fused)
    scan2_kernel<<<1, 32>>>();                     // 5
    scan3_kernel<<<nodeBlocks, 256>>>();           // 6
    fill_kernel<<<edgeBlocks, 256>>>(ei);          // 7
    agg1_kernel<<<aggBlocks, 256>>>(b1);           // 8
    gemm_wmma_kernel<<<gemmBlocks, 256, GEMM_SMEM>>>(nullptr, 1, 1);  // 9
    agg2_pool_kernel<<<aggBlocks, 256>>>(b2);      // 10
    fc_kernel<<<1, CH>>>(Wfc, bfc, out);           // 11
}

// round 14
// speedup vs baseline: 1.9218x; 1.0438x over previous
#include <cuda_runtime.h>
#include <cuda_bf16.h>
#include <mma.h>
#include <cstdint>

using namespace nvcuda;

#define N_NODES 100000
#define N_EDGES 1600000
#define CH 128
#define SCAN_TILE 1024
#define N_TILES ((N_NODES + SCAN_TILE - 1) / SCAN_TILE)   // 98

// ---------------- scratch (static device globals; no allocation) ----------------
__device__ uint32_t g_bufA16[N_NODES * 64];  // xw (unscaled), packed bf16x2 [N][64]
__device__ float    g_bufB[N_NODES * CH];    // h1 (agg1 output, fp32 for GEMM2)
__device__ int   g_deg[N_NODES];
__device__ float g_dinv[N_NODES];
__device__ int   g_rowptr[N_NODES + 1];
__device__ int   g_cursor[N_NODES];
__device__ int   g_col[N_EDGES];
__device__ int   g_tilesums[N_TILES];
__device__ float g_pool[CH];

// pre-split bf16 weights, row-major [k][n]  (128x128 bf16 = 32KB each)
__device__ __nv_bfloat16 g_W1_hi[CH * CH];
__device__ __nv_bfloat16 g_W1_lo[CH * CH];
__device__ __nv_bfloat16 g_W2_hi[CH * CH];
__device__ __nv_bfloat16 g_W2_lo[CH * CH];

__device__ __forceinline__ uint32_t pack_bf2(float a, float b) {
    __nv_bfloat162 t = __floats2bfloat162_rn(a, b);
    return *(uint32_t*)&t;
}

// ---------------- graph preprocessing ----------------

__global__ void init_kernel() {
    int v = blockIdx.x * blockDim.x + threadIdx.x;
    if (v < N_NODES) g_deg[v] = 1;          // self loop
    if (v < CH) g_pool[v] = 0.f;
}

__global__ void hist_kernel(const int* __restrict__ ei) {
    int e = blockIdx.x * blockDim.x + threadIdx.x;
    if (e < N_EDGES) atomicAdd(&g_deg[ei[N_EDGES + e]], 1);
}

// scan of (deg-1) -> tile-local rowptr + tile sums; dinv fused in
__global__ void scan1_kernel() {
    __shared__ int sh[SCAN_TILE];
    int t = threadIdx.x;
    int v = blockIdx.x * SCAN_TILE + t;
    int deg = (v < N_NODES) ? g_deg[v] : 1;
    int c = deg - 1;
    if (v < N_NODES) g_dinv[v] = rsqrtf((float)deg);
    sh[t] = c;
    __syncthreads();
    #pragma unroll
    for (int off = 1; off < SCAN_TILE; off <<= 1) {
        int val = (t >= off) ? sh[t - off] : 0;
        __syncthreads();
        sh[t] += val;
        __syncthreads();
    }
    if (v < N_NODES) g_rowptr[v] = sh[t] - c;
    if (t == SCAN_TILE - 1) g_tilesums[blockIdx.x] = sh[t];
}

__global__ void scan2_kernel() {
    if (threadIdx.x == 0) {
        int run = 0;
        for (int i = 0; i < N_TILES; ++i) { int tmp = g_tilesums[i]; g_tilesums[i] = run; run += tmp; }
    }
}

__global__ void scan3_kernel() {
    int v = blockIdx.x * blockDim.x + threadIdx.x;
    if (v < N_NODES) {
        int r = g_rowptr[v] + g_tilesums[v >> 10];
        g_rowptr[v] = r;
        g_cursor[v] = r;
    }
    if (v == 0) g_rowptr[N_NODES] = N_EDGES;
}

__global__ void fill_kernel(const int* __restrict__ ei) {
    int e = blockIdx.x * blockDim.x + threadIdx.x;
    if (e < N_EDGES) {
        int s = ei[e];
        int d = ei[N_EDGES + e];
        int p = atomicAdd(&g_cursor[d], 1);
        g_col[p] = s;
    }
}

// ---------------- weight prep: split W1,W2 into bf16 hi/lo (one elem/thread) ----------------
__global__ void wprep_kernel(const float* __restrict__ W1, const float* __restrict__ W2) {
    int idx = blockIdx.x * blockDim.x + threadIdx.x;     // 0..32767
    if (idx >= 2 * CH * CH) return;
    int layer = idx >> 14;
    int i = idx & (CH * CH - 1);
    float v = layer ? W2[i] : W1[i];
    __nv_bfloat16 h = __float2bfloat16(v);
    __nv_bfloat16 l = __float2bfloat16(v - __bfloat162float(h));
    if (layer) { g_W2_hi[i] = h; g_W2_lo[i] = l; }
    else       { g_W1_hi[i] = h; g_W1_lo[i] = l; }
}

// ---------------- GEMM via wmma: g_bufA16 = pack_bf16(A @ W) ----------------
// 2-pass precision: xw = bf16(a)*W_hi + bf16(a)*W_lo.
//   - W split kills SYSTEMATIC weight-quantization error (shared across nodes,
//     does not average out in the mean-pool).
//   - A-side bf16 rounding is node-random and averages out (measured: 4e-3
//     message rounding -> 2.8e-5 final).
// M-tile 64, 256 threads = 8 warps (2m x 4n), warp tile 32x32 (2x2 frags).
#define MT 64
#define LDT 136
#define SM_A   0
#define SM_BHI (MT * LDT)
#define SM_BLO (MT * LDT + 128 * LDT)
#define GEMM_SMEM ((MT * LDT + 2 * 128 * LDT) * 2)   // 87040 bytes

__global__ void __launch_bounds__(256, 2)
gemm_wmma_kernel(const float* __restrict__ Aext, int useInternal, int layer) {
    extern __shared__ __nv_bfloat16 sm[];
    const float* A = useInternal ? g_bufB : Aext;
    const __nv_bfloat16* Wh = (layer == 0) ? g_W1_hi : g_W2_hi;
    const __nv_bfloat16* Wl = (layer == 0) ? g_W1_lo : g_W2_lo;

    int tid = threadIdx.x;
    int row0 = blockIdx.x * MT;

    // ---- load A tile (64x128 fp32) -> single bf16, row-major padded ----
    #pragma unroll 4
    for (int i = 0; i < 16; ++i) {
        int p = tid + (i << 8);          // 0..4095 float2 slots
        int row = p >> 6;                // 0..63
        int cp  = p & 63;
        int gr = row0 + row;
        float2 v = (gr < N_NODES) ? ((const float2*)A)[gr * 64 + cp]
                                  : make_float2(0.f, 0.f);
        int o = row * LDT + cp * 2;
        *(uint32_t*)&sm[SM_A + o] = pack_bf2(v.x, v.y);
    }
    // ---- copy W tiles (128x128 bf16, 16B chunks into padded rows) ----
    #pragma unroll
    for (int i = 0; i < 8; ++i) {
        int j = tid + (i << 8);          // 0..2047 uint4 chunks
        int row = j >> 4, q = j & 15;
        int dst = (row * LDT + q * 8) >> 3;
        ((uint4*)(sm + SM_BHI))[dst] = ((const uint4*)Wh)[j];
        ((uint4*)(sm + SM_BLO))[dst] = ((const uint4*)Wl)[j];
    }
    __syncthreads();

    int w = tid >> 5;
    int wm = w >> 2;          // 0..1 -> rows [wm*32, +32)
    int wn = w & 3;           // 0..3 -> cols [wn*32, +32)

    wmma::fragment<wmma::accumulator, 16, 16, 16, float> acc[2][2];
    #pragma unroll
    for (int mi = 0; mi < 2; ++mi)
        #pragma unroll
        for (int nj = 0; nj < 2; ++nj)
            wmma::fill_fragment(acc[mi][nj], 0.f);

    #pragma unroll
    for (int kk = 0; kk < 8; ++kk) {
        wmma::fragment<wmma::matrix_b, 16, 16, 16, __nv_bfloat16, wmma::row_major> bhi[2], blo[2];
        #pragma unroll
        for (int nj = 0; nj < 2; ++nj) {
            int boff = (kk * 16) * LDT + wn * 32 + nj * 16;
            wmma::load_matrix_sync(bhi[nj], sm + SM_BHI + boff, LDT);
            wmma::load_matrix_sync(blo[nj], sm + SM_BLO + boff, LDT);
        }
        #pragma unroll
        for (int mi = 0; mi < 2; ++mi) {
            wmma::fragment<wmma::matrix_a, 16, 16, 16, __nv_bfloat16, wmma::row_major> a;
            int aoff = (wm * 32 + mi * 16) * LDT + kk * 16;
            wmma::load_matrix_sync(a, sm + SM_A + aoff, LDT);
            #pragma unroll
            for (int nj = 0; nj < 2; ++nj) {
                wmma::mma_sync(acc[mi][nj], a, bhi[nj], acc[mi][nj]);
                wmma::mma_sync(acc[mi][nj], a, blo[nj], acc[mi][nj]);
            }
        }
    }

    // ---- epilogue: park fp32 C (64x128 = 32KB) in smem, pack bf16x2, store ----
    __syncthreads();
    float* C = (float*)sm;
    #pragma unroll
    for (int mi = 0; mi < 2; ++mi)
        #pragma unroll
        for (int nj = 0; nj < 2; ++nj)
            wmma::store_matrix_sync(C + (wm * 32 + mi * 16) * 128 + wn * 32 + nj * 16,
                                    acc[mi][nj], 128, wmma::mem_row_major);
    __syncthreads();

    // each thread: one quarter-row = 32 floats -> 4 uint4 (disjoint slots)
    int r  = tid >> 2;                    // 0..63
    int qd = tid & 3;                     // 0..3
    int gr = row0 + r;
    if (gr < N_NODES) {
        const float4* cs = (const float4*)(C + r * 128) + qd * 8;   // 8 float4
        uint4* od = (uint4*)(g_bufA16 + gr * 64) + qd * 4;          // 4 uint4
        #pragma unroll
        for (int q = 0; q < 4; ++q) {
            float4 a = cs[q * 2 + 0];
            float4 b = cs[q * 2 + 1];
            uint4 o;
            o.x = pack_bf2(a.x, a.y);
            o.y = pack_bf2(a.z, a.w);
            o.z = pack_bf2(b.x, b.y);
            o.w = pack_bf2(b.z, b.w);
            od[q] = o;
        }
    }
}

// ---------------- aggregation helpers: acc += dinv_u * msg[u] ----------------
__device__ __forceinline__ void gather_fma(float4& acc, const uint2* __restrict__ base,
                                           float du, int u, int lane) {
    uint2 m = base[u * 32 + lane];
    __nv_bfloat162 p0 = *(__nv_bfloat162*)&m.x;
    __nv_bfloat162 p1 = *(__nv_bfloat162*)&m.y;
    float2 f0 = __bfloat1622float2(p0);
    float2 f1 = __bfloat1622float2(p1);
    acc.x = fmaf(du, f0.x, acc.x);
    acc.y = fmaf(du, f0.y, acc.y);
    acc.z = fmaf(du, f1.x, acc.z);
    acc.w = fmaf(du, f1.y, acc.w);
}

// ---------------- agg layer1: h1[v] = relu(dinv[v]*Σ dinv[u]*xw[u] + b) ----------------
__global__ void agg1_kernel(const float* __restrict__ bias) {
    int warp = (blockIdx.x * blockDim.x + threadIdx.x) >> 5;
    int lane = threadIdx.x & 31;
    if (warp >= N_NODES) return;
    int v = warp;
    const uint2* base = (const uint2*)g_bufA16;
    float dv = g_dinv[v];
    float4 acc = make_float4(0.f, 0.f, 0.f, 0.f);
    gather_fma(acc, base, dv, v, lane);               // self loop
    int s = g_rowptr[v], e = g_rowptr[v + 1];
    int i = s;
    for (; i + 3 < e; i += 4) {
        int u0 = g_col[i], u1 = g_col[i + 1], u2 = g_col[i + 2], u3 = g_col[i + 3];
        float d0 = g_dinv[u0], d1 = g_dinv[u1], d2 = g_dinv[u2], d3 = g_dinv[u3];
        gather_fma(acc, base, d0, u0, lane);
        gather_fma(acc, base, d1, u1, lane);
        gather_fma(acc, base, d2, u2, lane);
        gather_fma(acc, base, d3, u3, lane);
    }
    for (; i < e; ++i) {
        int u = g_col[i];
        gather_fma(acc, base, g_dinv[u], u, lane);
    }
    float4 bb = ((const float4*)bias)[lane];
    acc.x = fmaxf(fmaf(acc.x, dv, bb.x), 0.f);
    acc.y = fmaxf(fmaf(acc.y, dv, bb.y), 0.f);
    acc.z = fmaxf(fmaf(acc.z, dv, bb.z), 0.f);
    acc.w = fmaxf(fmaf(acc.w, dv, bb.w), 0.f);
    ((float4*)g_bufB)[v * 32 + lane] = acc;
}

// ---------------- agg layer2 + fused mean-pool (h2 never stored) ----------------
__global__ void agg2_pool_kernel(const float* __restrict__ bias) {
    __shared__ float sp[CH];
    int tid = threadIdx.x;
    if (tid < CH) sp[tid] = 0.f;
    __syncthreads();

    int warp = (blockIdx.x * blockDim.x + tid) >> 5;
    int lane = tid & 31;
    if (warp < N_NODES) {
        int v = warp;
        const uint2* base = (const uint2*)g_bufA16;
        float dv = g_dinv[v];
        float4 acc = make_float4(0.f, 0.f, 0.f, 0.f);
        gather_fma(acc, base, dv, v, lane);
        int s = g_rowptr[v], e = g_rowptr[v + 1];
        int i = s;
        for (; i + 3 < e; i += 4) {
            int u0 = g_col[i], u1 = g_col[i + 1], u2 = g_col[i + 2], u3 = g_col[i + 3];
            float d0 = g_dinv[u0], d1 = g_dinv[u1], d2 = g_dinv[u2], d3 = g_dinv[u3];
            gather_fma(acc, base, d0, u0, lane);
            gather_fma(acc, base, d1, u1, lane);
            gather_fma(acc, base, d2, u2, lane);
            gather_fma(acc, base, d3, u3, lane);
        }
        for (; i < e; ++i) {
            int u = g_col[i];
            gather_fma(acc, base, g_dinv[u], u, lane);
        }
        float4 bb = ((const float4*)bias)[lane];
        acc.x = fmaxf(fmaf(acc.x, dv, bb.x), 0.f);
        acc.y = fmaxf(fmaf(acc.y, dv, bb.y), 0.f);
        acc.z = fmaxf(fmaf(acc.z, dv, bb.z), 0.f);
        acc.w = fmaxf(fmaf(acc.w, dv, bb.w), 0.f);
        int c0 = lane * 4;
        atomicAdd(&sp[c0 + 0], acc.x);
        atomicAdd(&sp[c0 + 1], acc.y);
        atomicAdd(&sp[c0 + 2], acc.z);
        atomicAdd(&sp[c0 + 3], acc.w);
    }
    __syncthreads();
    if (tid < CH) atomicAdd(&g_pool[tid], sp[tid]);
}

// ---------------- final FC: out = (pool/N) @ Wfc + bfc ----------------
__global__ void fc_kernel(const float* __restrict__ Wfc,
                          const float* __restrict__ bfc,
                          float* __restrict__ out) {
    __shared__ float p[CH];
    int j = threadIdx.x;
    p[j] = g_pool[j] * (1.0f / (float)N_NODES);
    __syncthreads();
    float s = bfc[j];
    #pragma unroll 16
    for (int i = 0; i < CH; ++i)
        s += p[i] * Wfc[i * CH + j];
    out[j] = s;
}

// ---------------- launch ----------------
extern "C" void kernel_launch(void* const* d_in, const int* in_sizes, int n_in,
                              void* d_out, int out_size) {
    const float* x   = (const float*)d_in[0];
    const int*   ei  = (const int*)d_in[1];      // int32 (JAX demotes int64)
    const float* W1  = (const float*)d_in[2];
    const float* b1  = (const float*)d_in[3];
    const float* W2  = (const float*)d_in[4];
    const float* b2  = (const float*)d_in[5];
    const float* Wfc = (const float*)d_in[6];
    const float* bfc = (const float*)d_in[7];
    float* out = (float*)d_out;

    const int nodeBlocks = (N_NODES + 255) / 256;
    const int edgeBlocks = (N_EDGES + 255) / 256;
    const int gemmBlocks = (N_NODES + MT - 1) / MT;     // 1563
    const int aggBlocks  = (N_NODES * 32 + 255) / 256;  // 12500

    cudaFuncSetAttribute(gemm_wmma_kernel,
                         cudaFuncAttributeMaxDynamicSharedMemorySize, GEMM_SMEM);

    // gemm1 at our index 3 = ncu-profiled slot (harness offset 2)
    wprep_kernel<<<128, 256>>>(W1, W2);            // 0
    init_kernel<<<nodeBlocks, 256>>>();            // 1
    hist_kernel<<<edgeBlocks, 256>>>(ei);          // 2
    gemm_wmma_kernel<<<gemmBlocks, 256, GEMM_SMEM>>>(x, 0, 0);   // 3 <-- profiled
    scan1_kernel<<<N_TILES, SCAN_TILE>>>();        // 4 (dinv fused)
    scan2_kernel<<<1, 32>>>();                     // 5
    scan3_kernel<<<nodeBlocks, 256>>>();           // 6
    fill_kernel<<<edgeBlocks, 256>>>(ei);          // 7
    agg1_kernel<<<aggBlocks, 256>>>(b1);           // 8
    gemm_wmma_kernel<<<gemmBlocks, 256, GEMM_SMEM>>>(nullptr, 1, 1);  // 9
    agg2_pool_kernel<<<aggBlocks, 256>>>(b2);      // 10
    fc_kernel<<<1, CH>>>(Wfc, bfc, out);           // 11
}

// round 16
// speedup vs baseline: 1.9736x; 1.0270x over previous
#include <cuda_runtime.h>
#include <cuda_bf16.h>
#include <mma.h>
#include <cstdint>

using namespace nvcuda;

#define N_NODES 100000
#define N_EDGES 1600000
#define CH 128
#define SCAN_TILE 1024
#define N_TILES ((N_NODES + SCAN_TILE - 1) / SCAN_TILE)   // 98

// ---------------- scratch (static device globals; no allocation) ----------------
__device__ uint32_t g_bufA16[N_NODES * 64];  // xw (unscaled), packed bf16x2 [N][64]
__device__ uint32_t g_bufB16[N_NODES * 64];  // h1, packed bf16x2 [N][64]
__device__ int   g_deg[N_NODES];
__device__ float g_dinv[N_NODES];
__device__ int   g_rowptr[N_NODES + 1];
__device__ int   g_cursor[N_NODES];
__device__ int   g_col[N_EDGES];
__device__ int   g_tilesums[N_TILES];
__device__ float g_pool[CH];

// pre-split bf16 weights, row-major [k][n]  (128x128 bf16 = 32KB each)
__device__ __nv_bfloat16 g_W1_hi[CH * CH];
__device__ __nv_bfloat16 g_W1_lo[CH * CH];
__device__ __nv_bfloat16 g_W2_hi[CH * CH];
__device__ __nv_bfloat16 g_W2_lo[CH * CH];

__device__ __forceinline__ uint32_t pack_bf2(float a, float b) {
    __nv_bfloat162 t = __floats2bfloat162_rn(a, b);
    return *(uint32_t*)&t;
}

// ---------------- graph preprocessing ----------------

__global__ void init_kernel() {
    int v = blockIdx.x * blockDim.x + threadIdx.x;
    if (v < N_NODES) g_deg[v] = 1;          // self loop
    if (v < CH) g_pool[v] = 0.f;
}

// 4 edges per thread via int4 (N_EDGES % 4 == 0)
__global__ void hist_kernel(const int* __restrict__ ei) {
    int e4 = blockIdx.x * blockDim.x + threadIdx.x;
    if (e4 < N_EDGES / 4) {
        int4 d = ((const int4*)(ei + N_EDGES))[e4];
        atomicAdd(&g_deg[d.x], 1);
        atomicAdd(&g_deg[d.y], 1);
        atomicAdd(&g_deg[d.z], 1);
        atomicAdd(&g_deg[d.w], 1);
    }
}

// scan of (deg-1) -> tile-local rowptr + tile sums; dinv fused in
__global__ void scan1_kernel() {
    __shared__ int sh[SCAN_TILE];
    int t = threadIdx.x;
    int v = blockIdx.x * SCAN_TILE + t;
    int deg = (v < N_NODES) ? g_deg[v] : 1;
    int c = deg - 1;
    if (v < N_NODES) g_dinv[v] = rsqrtf((float)deg);
    sh[t] = c;
    __syncthreads();
    #pragma unroll
    for (int off = 1; off < SCAN_TILE; off <<= 1) {
        int val = (t >= off) ? sh[t - off] : 0;
        __syncthreads();
        sh[t] += val;
        __syncthreads();
    }
    if (v < N_NODES) g_rowptr[v] = sh[t] - c;
    if (t == SCAN_TILE - 1) g_tilesums[blockIdx.x] = sh[t];
}

__global__ void scan2_kernel() {
    if (threadIdx.x == 0) {
        int run = 0;
        for (int i = 0; i < N_TILES; ++i) { int tmp = g_tilesums[i]; g_tilesums[i] = run; run += tmp; }
    }
}

__global__ void scan3_kernel() {
    int v = blockIdx.x * blockDim.x + threadIdx.x;
    if (v < N_NODES) {
        int r = g_rowptr[v] + g_tilesums[v >> 10];
        g_rowptr[v] = r;
        g_cursor[v] = r;
    }
    if (v == 0) g_rowptr[N_NODES] = N_EDGES;
}

__global__ void fill_kernel(const int* __restrict__ ei) {
    int e4 = blockIdx.x * blockDim.x + threadIdx.x;
    if (e4 < N_EDGES / 4) {
        int4 s = ((const int4*)ei)[e4];
        int4 d = ((const int4*)(ei + N_EDGES))[e4];
        g_col[atomicAdd(&g_cursor[d.x], 1)] = s.x;
        g_col[atomicAdd(&g_cursor[d.y], 1)] = s.y;
        g_col[atomicAdd(&g_cursor[d.z], 1)] = s.z;
        g_col[atomicAdd(&g_cursor[d.w], 1)] = s.w;
    }
}

// ---------------- weight prep: split W1,W2 into bf16 hi/lo (one elem/thread) ----------------
__global__ void wprep_kernel(const float* __restrict__ W1, const float* __restrict__ W2) {
    int idx = blockIdx.x * blockDim.x + threadIdx.x;     // 0..32767
    if (idx >= 2 * CH * CH) return;
    int layer = idx >> 14;
    int i = idx & (CH * CH - 1);
    float v = layer ? W2[i] : W1[i];
    __nv_bfloat16 h = __float2bfloat16(v);
    __nv_bfloat16 l = __float2bfloat16(v - __bfloat162float(h));
    if (layer) { g_W2_hi[i] = h; g_W2_lo[i] = l; }
    else       { g_W1_hi[i] = h; g_W1_lo[i] = l; }
}

// ---------------- GEMM via wmma: g_bufA16 = pack_bf16(A @ W) ----------------
// 2-pass precision: xw = bf16(a)*W_hi + bf16(a)*W_lo.
// Layer 1: A = fp32 x (convert on load). Layer 2: A = bf16 h1 (pure copy).
#define MT 64
#define LDT 136
#define SM_A   0
#define SM_BHI (MT * LDT)
#define SM_BLO (MT * LDT + 128 * LDT)
#define GEMM_SMEM ((MT * LDT + 2 * 128 * LDT) * 2)   // 87040 bytes

__global__ void __launch_bounds__(256, 2)
gemm_wmma_kernel(const float* __restrict__ Aext, int useInternal, int layer) {
    extern __shared__ __nv_bfloat16 sm[];
    const __nv_bfloat16* Wh = (layer == 0) ? g_W1_hi : g_W2_hi;
    const __nv_bfloat16* Wl = (layer == 0) ? g_W1_lo : g_W2_lo;

    int tid = threadIdx.x;
    int row0 = blockIdx.x * MT;

    if (useInternal) {
        // ---- A tile from bf16 h1: pure uint4 copy (64 rows x 16 uint4) ----
        #pragma unroll
        for (int i = 0; i < 4; ++i) {
            int j = tid + (i << 8);          // 0..1023
            int row = j >> 4, q = j & 15;
            int gr = row0 + row;
            uint4 v = (gr < N_NODES) ? ((const uint4*)g_bufB16)[gr * 16 + q]
                                     : make_uint4(0u, 0u, 0u, 0u);
            ((uint4*)(sm + SM_A))[(row * LDT + q * 8) >> 3] = v;
        }
    } else {
        // ---- A tile from fp32 x: convert to bf16 on load ----
        #pragma unroll 4
        for (int i = 0; i < 16; ++i) {
            int p = tid + (i << 8);          // 0..4095 float2 slots
            int row = p >> 6;
            int cp  = p & 63;
            int gr = row0 + row;
            float2 v = (gr < N_NODES) ? ((const float2*)Aext)[gr * 64 + cp]
                                      : make_float2(0.f, 0.f);
            *(uint32_t*)&sm[SM_A + row * LDT + cp * 2] = pack_bf2(v.x, v.y);
        }
    }
    // ---- copy W tiles (128x128 bf16, 16B chunks into padded rows) ----
    #pragma unroll
    for (int i = 0; i < 8; ++i) {
        int j = tid + (i << 8);          // 0..2047 uint4 chunks
        int row = j >> 4, q = j & 15;
        int dst = (row * LDT + q * 8) >> 3;
        ((uint4*)(sm + SM_BHI))[dst] = ((const uint4*)Wh)[j];
        ((uint4*)(sm + SM_BLO))[dst] = ((const uint4*)Wl)[j];
    }
    __syncthreads();

    int w = tid >> 5;
    int wm = w >> 2;          // 0..1 -> rows [wm*32, +32)
    int wn = w & 3;           // 0..3 -> cols [wn*32, +32)

    wmma::fragment<wmma::accumulator, 16, 16, 16, float> acc[2][2];
    #pragma unroll
    for (int mi = 0; mi < 2; ++mi)
        #pragma unroll
        for (int nj = 0; nj < 2; ++nj)
            wmma::fill_fragment(acc[mi][nj], 0.f);

    #pragma unroll
    for (int kk = 0; kk < 8; ++kk) {
        wmma::fragment<wmma::matrix_b, 16, 16, 16, __nv_bfloat16, wmma::row_major> bhi[2], blo[2];
        #pragma unroll
        for (int nj = 0; nj < 2; ++nj) {
            int boff = (kk * 16) * LDT + wn * 32 + nj * 16;
            wmma::load_matrix_sync(bhi[nj], sm + SM_BHI + boff, LDT);
            wmma::load_matrix_sync(blo[nj], sm + SM_BLO + boff, LDT);
        }
        #pragma unroll
        for (int mi = 0; mi < 2; ++mi) {
            wmma::fragment<wmma::matrix_a, 16, 16, 16, __nv_bfloat16, wmma::row_major> a;
            int aoff = (wm * 32 + mi * 16) * LDT + kk * 16;
            wmma::load_matrix_sync(a, sm + SM_A + aoff, LDT);
            #pragma unroll
            for (int nj = 0; nj < 2; ++nj) {
                wmma::mma_sync(acc[mi][nj], a, bhi[nj], acc[mi][nj]);
                wmma::mma_sync(acc[mi][nj], a, blo[nj], acc[mi][nj]);
            }
        }
    }

    // ---- epilogue: park fp32 C (64x128 = 32KB) in smem, pack bf16x2, store ----
    __syncthreads();
    float* C = (float*)sm;
    #pragma unroll
    for (int mi = 0; mi < 2; ++mi)
        #pragma unroll
        for (int nj = 0; nj < 2; ++nj)
            wmma::store_matrix_sync(C + (wm * 32 + mi * 16) * 128 + wn * 32 + nj * 16,
                                    acc[mi][nj], 128, wmma::mem_row_major);
    __syncthreads();

    // each thread: one quarter-row = 32 floats -> 4 uint4 (disjoint slots)
    int r  = tid >> 2;                    // 0..63
    int qd = tid & 3;                     // 0..3
    int gr = row0 + r;
    if (gr < N_NODES) {
        const float4* cs = (const float4*)(C + r * 128) + qd * 8;   // 8 float4
        uint4* od = (uint4*)(g_bufA16 + gr * 64) + qd * 4;          // 4 uint4
        #pragma unroll
        for (int q = 0; q < 4; ++q) {
            float4 a = cs[q * 2 + 0];
            float4 b = cs[q * 2 + 1];
            uint4 o;
            o.x = pack_bf2(a.x, a.y);
            o.y = pack_bf2(a.z, a.w);
            o.z = pack_bf2(b.x, b.y);
            o.w = pack_bf2(b.z, b.w);
            od[q] = o;
        }
    }
}

// ---------------- aggregation helpers: acc += dinv_u * msg[u] ----------------
__device__ __forceinline__ void gather_fma(float4& acc, const uint2* __restrict__ base,
                                           float du, int u, int lane) {
    uint2 m = base[u * 32 + lane];
    __nv_bfloat162 p0 = *(__nv_bfloat162*)&m.x;
    __nv_bfloat162 p1 = *(__nv_bfloat162*)&m.y;
    float2 f0 = __bfloat1622float2(p0);
    float2 f1 = __bfloat1622float2(p1);
    acc.x = fmaf(du, f0.x, acc.x);
    acc.y = fmaf(du, f0.y, acc.y);
    acc.z = fmaf(du, f1.x, acc.z);
    acc.w = fmaf(du, f1.y, acc.w);
}

// ---------------- agg layer1: h1[v] = relu(dinv[v]*Σ dinv[u]*xw[u] + b) -> bf16 ----------------
__global__ void agg1_kernel(const float* __restrict__ bias) {
    int warp = (blockIdx.x * blockDim.x + threadIdx.x) >> 5;
    int lane = threadIdx.x & 31;
    if (warp >= N_NODES) return;
    int v = warp;
    const uint2* base = (const uint2*)g_bufA16;
    float dv = g_dinv[v];
    float4 acc = make_float4(0.f, 0.f, 0.f, 0.f);
    gather_fma(acc, base, dv, v, lane);               // self loop
    int s = g_rowptr[v], e = g_rowptr[v + 1];
    int i = s;
    for (; i + 3 < e; i += 4) {
        int u0 = g_col[i], u1 = g_col[i + 1], u2 = g_col[i + 2], u3 = g_col[i + 3];
        float d0 = g_dinv[u0], d1 = g_dinv[u1], d2 = g_dinv[u2], d3 = g_dinv[u3];
        gather_fma(acc, base, d0, u0, lane);
        gather_fma(acc, base, d1, u1, lane);
        gather_fma(acc, base, d2, u2, lane);
        gather_fma(acc, base, d3, u3, lane);
    }
    for (; i < e; ++i) {
        int u = g_col[i];
        gather_fma(acc, base, g_dinv[u], u, lane);
    }
    float4 bb = ((const float4*)bias)[lane];
    acc.x = fmaxf(fmaf(acc.x, dv, bb.x), 0.f);
    acc.y = fmaxf(fmaf(acc.y, dv, bb.y), 0.f);
    acc.z = fmaxf(fmaf(acc.z, dv, bb.z), 0.f);
    acc.w = fmaxf(fmaf(acc.w, dv, bb.w), 0.f);
    // pack to bf16 here; GEMM2 would round to bf16 anyway -> identical numerics
    uint2 o;
    o.x = pack_bf2(acc.x, acc.y);
    o.y = pack_bf2(acc.z, acc.w);
    ((uint2*)g_bufB16)[v * 32 + lane] = o;
}

// ---------------- agg layer2 + fused mean-pool (h2 never stored) ----------------
__global__ void agg2_pool_kernel(const float* __restrict__ bias) {
    __shared__ float sp[CH];
    int tid = threadIdx.x;
    if (tid < CH) sp[tid] = 0.f;
    __syncthreads();

    int warp = (blockIdx.x * blockDim.x + tid) >> 5;
    int lane = tid & 31;
    if (warp < N_NODES) {
        int v = warp;
        const uint2* base = (const uint2*)g_bufA16;
        float dv = g_dinv[v];
        float4 acc = make_float4(0.f, 0.f, 0.f, 0.f);
        gather_fma(acc, base, dv, v, lane);
        int s = g_rowptr[v], e = g_rowptr[v + 1];
        int i = s;
        for (; i + 3 < e; i += 4) {
            int u0 = g_col[i], u1 = g_col[i + 1], u2 = g_col[i + 2], u3 = g_col[i + 3];
            float d0 = g_dinv[u0], d1 = g_dinv[u1], d2 = g_dinv[u2], d3 = g_dinv[u3];
            gather_fma(acc, base, d0, u0, lane);
            gather_fma(acc, base, d1, u1, lane);
            gather_fma(acc, base, d2, u2, lane);
            gather_fma(acc, base, d3, u3, lane);
        }
        for (; i < e; ++i) {
            int u = g_col[i];
            gather_fma(acc, base, g_dinv[u], u, lane);
        }
        float4 bb = ((const float4*)bias)[lane];
        acc.x = fmaxf(fmaf(acc.x, dv, bb.x), 0.f);
        acc.y = fmaxf(fmaf(acc.y, dv, bb.y), 0.f);
        acc.z = fmaxf(fmaf(acc.z, dv, bb.z), 0.f);
        acc.w = fmaxf(fmaf(acc.w, dv, bb.w), 0.f);
        int c0 = lane * 4;
        atomicAdd(&sp[c0 + 0], acc.x);
        atomicAdd(&sp[c0 + 1], acc.y);
        atomicAdd(&sp[c0 + 2], acc.z);
        atomicAdd(&sp[c0 + 3], acc.w);
    }
    __syncthreads();
    if (tid < CH) atomicAdd(&g_pool[tid], sp[tid]);
}

// ---------------- final FC: out = (pool/N) @ Wfc + bfc ----------------
__global__ void fc_kernel(const float* __restrict__ Wfc,
                          const float* __restrict__ bfc,
                          float* __restrict__ out) {
    __shared__ float p[CH];
    int j = threadIdx.x;
    p[j] = g_pool[j] * (1.0f / (float)N_NODES);
    __syncthreads();
    float s = bfc[j];
    #pragma unroll 16
    for (int i = 0; i < CH; ++i)
        s += p[i] * Wfc[i * CH + j];
    out[j] = s;
}

// ---------------- launch ----------------
extern "C" void kernel_launch(void* const* d_in, const int* in_sizes, int n_in,
                              void* d_out, int out_size) {
    const float* x   = (const float*)d_in[0];
    const int*   ei  = (const int*)d_in[1];      // int32 (JAX demotes int64)
    const float* W1  = (const float*)d_in[2];
    const float* b1  = (const float*)d_in[3];
    const float* W2  = (const float*)d_in[4];
    const float* b2  = (const float*)d_in[5];
    const float* Wfc = (const float*)d_in[6];
    const float* bfc = (const float*)d_in[7];
    float* out = (float*)d_out;

    const int nodeBlocks  = (N_NODES + 255) / 256;
    const int edge4Blocks = (N_EDGES / 4 + 255) / 256;   // 1563
    const int gemmBlocks  = (N_NODES + MT - 1) / MT;     // 1563
    const int aggBlocks   = (N_NODES * 32 + 255) / 256;  // 12500

    cudaFuncSetAttribute(gemm_wmma_kernel,
                         cudaFuncAttributeMaxDynamicSharedMemorySize, GEMM_SMEM);

    // gemm1 at our index 3 = ncu-profiled slot (harness offset 2)
    wprep_kernel<<<128, 256>>>(W1, W2);            // 0
    init_kernel<<<nodeBlocks, 256>>>();            // 1
    hist_kernel<<<edge4Blocks, 256>>>(ei);         // 2
    gemm_wmma_kernel<<<gemmBlocks, 256, GEMM_SMEM>>>(x, 0, 0);   // 3 <-- profiled
    scan1_kernel<<<N_TILES, SCAN_TILE>>>();        // 4 (dinv fused)
    scan2_kernel<<<1, 32>>>();                     // 5
    scan3_kernel<<<nodeBlocks, 256>>>();           // 6
    fill_kernel<<<edge4Blocks, 256>>>(ei);         // 7
    agg1_kernel<<<aggBlocks, 256>>>(b1);           // 8
    gemm_wmma_kernel<<<gemmBlocks, 256, GEMM_SMEM>>>(nullptr, 1, 1);  // 9
    agg2_pool_kernel<<<aggBlocks, 256>>>(b2);      // 10
    fc_kernel<<<1, CH>>>(Wfc, bfc, out);           // 11
}

// round 17
// speedup vs baseline: 2.0110x; 1.0190x over previous
#include <cuda_runtime.h>
#include <cuda_bf16.h>
#include <mma.h>
#include <cstdint>

using namespace nvcuda;

#define N_NODES 100000
#define N_EDGES 1600000
#define CH 128
#define SCAN_TILE 1024
#define N_TILES ((N_NODES + SCAN_TILE - 1) / SCAN_TILE)   // 98

// ---------------- scratch (static device globals; no allocation) ----------------
__device__ uint32_t g_bufA16[N_NODES * 64];  // xw (unscaled), packed bf16x2 [N][64]
__device__ uint32_t g_bufB16[N_NODES * 64];  // h1, packed bf16x2 [N][64]
__device__ int   g_deg[N_NODES];
__device__ float g_dinv[N_NODES];
__device__ int   g_rowptr[N_NODES + 1];
__device__ int   g_cursor[N_NODES];
__device__ int   g_col[N_EDGES];
__device__ int   g_tilesums[N_TILES];
__device__ float g_pool[CH];

// pre-split bf16 weights, row-major [k][n]  (128x128 bf16 = 32KB each)
__device__ __nv_bfloat16 g_W1_hi[CH * CH];
__device__ __nv_bfloat16 g_W1_lo[CH * CH];
__device__ __nv_bfloat16 g_W2_hi[CH * CH];
__device__ __nv_bfloat16 g_W2_lo[CH * CH];

__device__ __forceinline__ uint32_t pack_bf2(float a, float b) {
    __nv_bfloat162 t = __floats2bfloat162_rn(a, b);
    return *(uint32_t*)&t;
}

// ---------------- graph preprocessing ----------------

__global__ void init_kernel() {
    int v = blockIdx.x * blockDim.x + threadIdx.x;
    if (v < N_NODES) g_deg[v] = 1;          // self loop
    if (v < CH) g_pool[v] = 0.f;
}

// 4 edges per thread via int4 (N_EDGES % 4 == 0)
__global__ void hist_kernel(const int* __restrict__ ei) {
    int e4 = blockIdx.x * blockDim.x + threadIdx.x;
    if (e4 < N_EDGES / 4) {
        int4 d = ((const int4*)(ei + N_EDGES))[e4];
        atomicAdd(&g_deg[d.x], 1);
        atomicAdd(&g_deg[d.y], 1);
        atomicAdd(&g_deg[d.z], 1);
        atomicAdd(&g_deg[d.w], 1);
    }
}

// scan of (deg-1) -> tile-local rowptr + tile sums; dinv fused in
__global__ void scan1_kernel() {
    __shared__ int sh[SCAN_TILE];
    int t = threadIdx.x;
    int v = blockIdx.x * SCAN_TILE + t;
    int deg = (v < N_NODES) ? g_deg[v] : 1;
    int c = deg - 1;
    if (v < N_NODES) g_dinv[v] = rsqrtf((float)deg);
    sh[t] = c;
    __syncthreads();
    #pragma unroll
    for (int off = 1; off < SCAN_TILE; off <<= 1) {
        int val = (t >= off) ? sh[t - off] : 0;
        __syncthreads();
        sh[t] += val;
        __syncthreads();
    }
    if (v < N_NODES) g_rowptr[v] = sh[t] - c;
    if (t == SCAN_TILE - 1) g_tilesums[blockIdx.x] = sh[t];
}

__global__ void scan2_kernel() {
    if (threadIdx.x == 0) {
        int run = 0;
        for (int i = 0; i < N_TILES; ++i) { int tmp = g_tilesums[i]; g_tilesums[i] = run; run += tmp; }
    }
}

__global__ void scan3_kernel() {
    int v = blockIdx.x * blockDim.x + threadIdx.x;
    if (v < N_NODES) {
        int r = g_rowptr[v] + g_tilesums[v >> 10];
        g_rowptr[v] = r;
        g_cursor[v] = r;
    }
    if (v == 0) g_rowptr[N_NODES] = N_EDGES;
}

__global__ void fill_kernel(const int* __restrict__ ei) {
    int e4 = blockIdx.x * blockDim.x + threadIdx.x;
    if (e4 < N_EDGES / 4) {
        int4 s = ((const int4*)ei)[e4];
        int4 d = ((const int4*)(ei + N_EDGES))[e4];
        g_col[atomicAdd(&g_cursor[d.x], 1)] = s.x;
        g_col[atomicAdd(&g_cursor[d.y], 1)] = s.y;
        g_col[atomicAdd(&g_cursor[d.z], 1)] = s.z;
        g_col[atomicAdd(&g_cursor[d.w], 1)] = s.w;
    }
}

// ---------------- weight prep: split W1,W2 into bf16 hi/lo (one elem/thread) ----------------
__global__ void wprep_kernel(const float* __restrict__ W1, const float* __restrict__ W2) {
    int idx = blockIdx.x * blockDim.x + threadIdx.x;     // 0..32767
    if (idx >= 2 * CH * CH) return;
    int layer = idx >> 14;
    int i = idx & (CH * CH - 1);
    float v = layer ? W2[i] : W1[i];
    __nv_bfloat16 h = __float2bfloat16(v);
    __nv_bfloat16 l = __float2bfloat16(v - __bfloat162float(h));
    if (layer) { g_W2_hi[i] = h; g_W2_lo[i] = l; }
    else       { g_W1_hi[i] = h; g_W1_lo[i] = l; }
}

// ---------------- GEMM via wmma: g_bufA16 = pack_bf16(A @ W) ----------------
// 2-pass precision: xw = bf16(a)*W_hi + bf16(a)*W_lo.
// Layer 1: A = fp32 x (convert on load). Layer 2: A = bf16 h1 (pure copy).
#define MT 64
#define LDT 136
#define SM_A   0
#define SM_BHI (MT * LDT)
#define SM_BLO (MT * LDT + 128 * LDT)
#define GEMM_SMEM ((MT * LDT + 2 * 128 * LDT) * 2)   // 87040 bytes

__global__ void __launch_bounds__(256, 2)
gemm_wmma_kernel(const float* __restrict__ Aext, int useInternal, int layer) {
    extern __shared__ __nv_bfloat16 sm[];
    const __nv_bfloat16* Wh = (layer == 0) ? g_W1_hi : g_W2_hi;
    const __nv_bfloat16* Wl = (layer == 0) ? g_W1_lo : g_W2_lo;

    int tid = threadIdx.x;
    int row0 = blockIdx.x * MT;

    if (useInternal) {
        // ---- A tile from bf16 h1: pure uint4 copy (64 rows x 16 uint4) ----
        #pragma unroll
        for (int i = 0; i < 4; ++i) {
            int j = tid + (i << 8);          // 0..1023
            int row = j >> 4, q = j & 15;
            int gr = row0 + row;
            uint4 v = (gr < N_NODES) ? ((const uint4*)g_bufB16)[gr * 16 + q]
                                     : make_uint4(0u, 0u, 0u, 0u);
            ((uint4*)(sm + SM_A))[(row * LDT + q * 8) >> 3] = v;
        }
    } else {
        // ---- A tile from fp32 x: convert to bf16 on load ----
        #pragma unroll 4
        for (int i = 0; i < 16; ++i) {
            int p = tid + (i << 8);          // 0..4095 float2 slots
            int row = p >> 6;
            int cp  = p & 63;
            int gr = row0 + row;
            float2 v = (gr < N_NODES) ? ((const float2*)Aext)[gr * 64 + cp]
                                      : make_float2(0.f, 0.f);
            *(uint32_t*)&sm[SM_A + row * LDT + cp * 2] = pack_bf2(v.x, v.y);
        }
    }
    // ---- copy W tiles (128x128 bf16, 16B chunks into padded rows) ----
    #pragma unroll
    for (int i = 0; i < 8; ++i) {
        int j = tid + (i << 8);          // 0..2047 uint4 chunks
        int row = j >> 4, q = j & 15;
        int dst = (row * LDT + q * 8) >> 3;
        ((uint4*)(sm + SM_BHI))[dst] = ((const uint4*)Wh)[j];
        ((uint4*)(sm + SM_BLO))[dst] = ((const uint4*)Wl)[j];
    }
    __syncthreads();

    int w = tid >> 5;
    int wm = w >> 2;          // 0..1 -> rows [wm*32, +32)
    int wn = w & 3;           // 0..3 -> cols [wn*32, +32)

    wmma::fragment<wmma::accumulator, 16, 16, 16, float> acc[2][2];
    #pragma unroll
    for (int mi = 0; mi < 2; ++mi)
        #pragma unroll
        for (int nj = 0; nj < 2; ++nj)
            wmma::fill_fragment(acc[mi][nj], 0.f);

    #pragma unroll
    for (int kk = 0; kk < 8; ++kk) {
        wmma::fragment<wmma::matrix_b, 16, 16, 16, __nv_bfloat16, wmma::row_major> bhi[2], blo[2];
        #pragma unroll
        for (int nj = 0; nj < 2; ++nj) {
            int boff = (kk * 16) * LDT + wn * 32 + nj * 16;
            wmma::load_matrix_sync(bhi[nj], sm + SM_BHI + boff, LDT);
            wmma::load_matrix_sync(blo[nj], sm + SM_BLO + boff, LDT);
        }
        #pragma unroll
        for (int mi = 0; mi < 2; ++mi) {
            wmma::fragment<wmma::matrix_a, 16, 16, 16, __nv_bfloat16, wmma::row_major> a;
            int aoff = (wm * 32 + mi * 16) * LDT + kk * 16;
            wmma::load_matrix_sync(a, sm + SM_A + aoff, LDT);
            #pragma unroll
            for (int nj = 0; nj < 2; ++nj) {
                wmma::mma_sync(acc[mi][nj], a, bhi[nj], acc[mi][nj]);
                wmma::mma_sync(acc[mi][nj], a, blo[nj], acc[mi][nj]);
            }
        }
    }

    // ---- epilogue: park fp32 C (64x128 = 32KB) in smem, pack bf16x2, store ----
    __syncthreads();
    float* C = (float*)sm;
    #pragma unroll
    for (int mi = 0; mi < 2; ++mi)
        #pragma unroll
        for (int nj = 0; nj < 2; ++nj)
            wmma::store_matrix_sync(C + (wm * 32 + mi * 16) * 128 + wn * 32 + nj * 16,
                                    acc[mi][nj], 128, wmma::mem_row_major);
    __syncthreads();

    // each thread: one quarter-row = 32 floats -> 4 uint4 (disjoint slots)
    int r  = tid >> 2;                    // 0..63
    int qd = tid & 3;                     // 0..3
    int gr = row0 + r;
    if (gr < N_NODES) {
        const float4* cs = (const float4*)(C + r * 128) + qd * 8;   // 8 float4
        uint4* od = (uint4*)(g_bufA16 + gr * 64) + qd * 4;          // 4 uint4
        #pragma unroll
        for (int q = 0; q < 4; ++q) {
            float4 a = cs[q * 2 + 0];
            float4 b = cs[q * 2 + 1];
            uint4 o;
            o.x = pack_bf2(a.x, a.y);
            o.y = pack_bf2(a.z, a.w);
            o.z = pack_bf2(b.x, b.y);
            o.w = pack_bf2(b.z, b.w);
            od[q] = o;
        }
    }
}

// ---------------- aggregation helpers: acc += dinv_u * msg[u] ----------------
__device__ __forceinline__ void gather_fma(float4& acc, const uint2* __restrict__ base,
                                           float du, int u, int lane) {
    uint2 m = base[u * 32 + lane];
    __nv_bfloat162 p0 = *(__nv_bfloat162*)&m.x;
    __nv_bfloat162 p1 = *(__nv_bfloat162*)&m.y;
    float2 f0 = __bfloat1622float2(p0);
    float2 f1 = __bfloat1622float2(p1);
    acc.x = fmaf(du, f0.x, acc.x);
    acc.y = fmaf(du, f0.y, acc.y);
    acc.z = fmaf(du, f1.x, acc.z);
    acc.w = fmaf(du, f1.y, acc.w);
}

// ---------------- agg layer1: h1[v] = relu(dinv[v]*Σ dinv[u]*xw[u] + b) -> bf16 ----------------
__global__ void agg1_kernel(const float* __restrict__ bias) {
    int warp = (blockIdx.x * blockDim.x + threadIdx.x) >> 5;
    int lane = threadIdx.x & 31;
    if (warp >= N_NODES) return;
    int v = warp;
    const uint2* base = (const uint2*)g_bufA16;
    float dv = g_dinv[v];
    float4 acc = make_float4(0.f, 0.f, 0.f, 0.f);
    gather_fma(acc, base, dv, v, lane);               // self loop
    int s = g_rowptr[v], e = g_rowptr[v + 1];
    int i = s;
    for (; i + 3 < e; i += 4) {
        int u0 = g_col[i], u1 = g_col[i + 1], u2 = g_col[i + 2], u3 = g_col[i + 3];
        float d0 = g_dinv[u0], d1 = g_dinv[u1], d2 = g_dinv[u2], d3 = g_dinv[u3];
        gather_fma(acc, base, d0, u0, lane);
        gather_fma(acc, base, d1, u1, lane);
        gather_fma(acc, base, d2, u2, lane);
        gather_fma(acc, base, d3, u3, lane);
    }
    for (; i < e; ++i) {
        int u = g_col[i];
        gather_fma(acc, base, g_dinv[u], u, lane);
    }
    float4 bb = ((const float4*)bias)[lane];
    acc.x = fmaxf(fmaf(acc.x, dv, bb.x), 0.f);
    acc.y = fmaxf(fmaf(acc.y, dv, bb.y), 0.f);
    acc.z = fmaxf(fmaf(acc.z, dv, bb.z), 0.f);
    acc.w = fmaxf(fmaf(acc.w, dv, bb.w), 0.f);
    // pack to bf16 here; GEMM2 would round to bf16 anyway -> identical numerics
    uint2 o;
    o.x = pack_bf2(acc.x, acc.y);
    o.y = pack_bf2(acc.z, acc.w);
    ((uint2*)g_bufB16)[v * 32 + lane] = o;
}

// ---------------- agg layer2 + fused mean-pool (h2 never stored) ----------------
__global__ void agg2_pool_kernel(const float* __restrict__ bias) {
    __shared__ float sp[CH];
    int tid = threadIdx.x;
    if (tid < CH) sp[tid] = 0.f;
    __syncthreads();

    int warp = (blockIdx.x * blockDim.x + tid) >> 5;
    int lane = tid & 31;
    if (warp < N_NODES) {
        int v = warp;
        const uint2* base = (const uint2*)g_bufA16;
        float dv = g_dinv[v];
        float4 acc = make_float4(0.f, 0.f, 0.f, 0.f);
        gather_fma(acc, base, dv, v, lane);
        int s = g_rowptr[v], e = g_rowptr[v + 1];
        int i = s;
        for (; i + 3 < e; i += 4) {
            int u0 = g_col[i], u1 = g_col[i + 1], u2 = g_col[i + 2], u3 = g_col[i + 3];
            float d0 = g_dinv[u0], d1 = g_dinv[u1], d2 = g_dinv[u2], d3 = g_dinv[u3];
            gather_fma(acc, base, d0, u0, lane);
            gather_fma(acc, base, d1, u1, lane);
            gather_fma(acc, base, d2, u2, lane);
            gather_fma(acc, base, d3, u3, lane);
        }
        for (; i < e; ++i) {
            int u = g_col[i];
            gather_fma(acc, base, g_dinv[u], u, lane);
        }
        float4 bb = ((const float4*)bias)[lane];
        acc.x = fmaxf(fmaf(acc.x, dv, bb.x), 0.f);
        acc.y = fmaxf(fmaf(acc.y, dv, bb.y), 0.f);
        acc.z = fmaxf(fmaf(acc.z, dv, bb.z), 0.f);
        acc.w = fmaxf(fmaf(acc.w, dv, bb.w), 0.f);
        int c0 = lane * 4;
        atomicAdd(&sp[c0 + 0], acc.x);
        atomicAdd(&sp[c0 + 1], acc.y);
        atomicAdd(&sp[c0 + 2], acc.z);
        atomicAdd(&sp[c0 + 3], acc.w);
    }
    __syncthreads();
    if (tid < CH) atomicAdd(&g_pool[tid], sp[tid]);
}

// ---------------- final FC: out = (pool/N) @ Wfc + bfc ----------------
__global__ void fc_kernel(const float* __restrict__ Wfc,
                          const float* __restrict__ bfc,
                          float* __restrict__ out) {
    __shared__ float p[CH];
    int j = threadIdx.x;
    p[j] = g_pool[j] * (1.0f / (float)N_NODES);
    __syncthreads();
    float s = bfc[j];
    #pragma unroll 16
    for (int i = 0; i < CH; ++i)
        s += p[i] * Wfc[i * CH + j];
    out[j] = s;
}

// ---------------- launch: dual-stream fork (prep || gemm1), capture-safe ----------------
extern "C" void kernel_launch(void* const* d_in, const int* in_sizes, int n_in,
                              void* d_out, int out_size) {
    const float* x   = (const float*)d_in[0];
    const int*   ei  = (const int*)d_in[1];      // int32 (JAX demotes int64)
    const float* W1  = (const float*)d_in[2];
    const float* b1  = (const float*)d_in[3];
    const float* W2  = (const float*)d_in[4];
    const float* b2  = (const float*)d_in[5];
    const float* Wfc = (const float*)d_in[6];
    const float* bfc = (const float*)d_in[7];
    float* out = (float*)d_out;

    const int nodeBlocks  = (N_NODES + 255) / 256;
    const int edge4Blocks = (N_EDGES / 4 + 255) / 256;   // 1563
    const int gemmBlocks  = (N_NODES + MT - 1) / MT;     // 1563
    const int aggBlocks   = (N_NODES * 32 + 255) / 256;  // 12500

    // lazy one-time creation (correctness run happens before graph capture)
    static cudaStream_t s2 = nullptr;
    static cudaEvent_t evRoot = nullptr, evPrep = nullptr;
    if (!s2) {
        cudaStreamCreateWithFlags(&s2, cudaStreamNonBlocking);
        cudaEventCreateWithFlags(&evRoot, cudaEventDisableTiming);
        cudaEventCreateWithFlags(&evPrep, cudaEventDisableTiming);
        cudaFuncSetAttribute(gemm_wmma_kernel,
                             cudaFuncAttributeMaxDynamicSharedMemorySize, GEMM_SMEM);
    }

    // fork: branch A (default stream) = wprep -> gemm1
    //       branch B (s2)             = init -> hist -> scan1..3 -> fill
    cudaEventRecord(evRoot, 0);
    cudaStreamWaitEvent(s2, evRoot, 0);

    init_kernel<<<nodeBlocks, 256, 0, s2>>>();
    hist_kernel<<<edge4Blocks, 256, 0, s2>>>(ei);

    wprep_kernel<<<128, 256>>>(W1, W2);
    gemm_wmma_kernel<<<gemmBlocks, 256, GEMM_SMEM>>>(x, 0, 0);

    scan1_kernel<<<N_TILES, SCAN_TILE, 0, s2>>>();
    scan2_kernel<<<1, 32, 0, s2>>>();
    scan3_kernel<<<nodeBlocks, 256, 0, s2>>>();
    fill_kernel<<<edge4Blocks, 256, 0, s2>>>(ei);
    cudaEventRecord(evPrep, s2);

    // join, then the strict chain on the default stream
    cudaStreamWaitEvent(0, evPrep, 0);
    agg1_kernel<<<aggBlocks, 256>>>(b1);
    gemm_wmma_kernel<<<gemmBlocks, 256, GEMM_SMEM>>>(nullptr, 1, 1);
    agg2_pool_kernel<<<aggBlocks, 256>>>(b2);
    fc_kernel<<<1, CH>>>(Wfc, bfc, out);
}